// round 2
// baseline (speedup 1.0000x reference)
#include <cuda_runtime.h>
#include <math.h>

#define B_  4
#define T_  4096
#define C_  1024
#define H_  64
#define BT  (B_*T_)
#define PAD 68   // 64 + 4, keeps float4 alignment, reduces smem bank conflicts

// Scratch for projected q,k,v (no cudaMalloc allowed)
__device__ float g_q[BT*H_];
__device__ float g_k[BT*H_];
__device__ float g_v[BT*H_];

// ---------------------------------------------------------------------------
// Kernel 1: fused QKV projection.  out[row][h] = sum_c x[row][c] * W[h][c]
// grid = (BT/64, 3), block = 256.  blockIdx.y selects Wq/Wk/Wv.
// 64x64 output tile, K-chunks of 16, 4x4 register microtiles.
// ---------------------------------------------------------------------------
__global__ __launch_bounds__(256) void proj_kernel(
        const float* __restrict__ x,
        const float* __restrict__ Wq,
        const float* __restrict__ Wk,
        const float* __restrict__ Wv)
{
    __shared__ float xs[64][20];
    __shared__ float ws[64][20];

    const float* W   = (blockIdx.y == 0) ? Wq : (blockIdx.y == 1) ? Wk : Wv;
    float*       out = (blockIdx.y == 0) ? g_q : (blockIdx.y == 1) ? g_k : g_v;

    const int tid  = threadIdx.x;
    const int ty   = tid >> 4;          // 0..15
    const int tx   = tid & 15;          // 0..15
    const int row0 = blockIdx.x * 64;

    const int lrow = tid >> 2;          // 0..63
    const int lc4  = (tid & 3) * 4;     // 0,4,8,12

    float acc[4][4] = {};

    for (int k0 = 0; k0 < C_; k0 += 16) {
        float4 xv = *(const float4*)&x[(size_t)(row0 + lrow) * C_ + k0 + lc4];
        float4 wv = *(const float4*)&W[(size_t)lrow * C_ + k0 + lc4];
        *(float4*)&xs[lrow][lc4] = xv;
        *(float4*)&ws[lrow][lc4] = wv;
        __syncthreads();

        #pragma unroll
        for (int kk = 0; kk < 16; kk++) {
            float a[4], b[4];
            #pragma unroll
            for (int i = 0; i < 4; i++) a[i] = xs[ty*4 + i][kk];
            #pragma unroll
            for (int j = 0; j < 4; j++) b[j] = ws[tx*4 + j][kk];
            #pragma unroll
            for (int i = 0; i < 4; i++)
                #pragma unroll
                for (int j = 0; j < 4; j++)
                    acc[i][j] += a[i] * b[j];
        }
        __syncthreads();
    }

    #pragma unroll
    for (int i = 0; i < 4; i++)
        #pragma unroll
        for (int j = 0; j < 4; j++)
            out[(size_t)(row0 + ty*4 + i) * H_ + tx*4 + j] = acc[i][j];
}

// ---------------------------------------------------------------------------
// Kernel 2: flash-attention, causal.  grid = (T/64, B), block = 256.
// BM=64 query rows per block, BN=64 key rows per tile, head dim 64.
// Online softmax; P staged via smem; 4x4 microtiles for S=QK^T and O=PV.
// Dynamic smem: Q,K,V,P each [64][PAD] floats = 69632 bytes.
// ---------------------------------------------------------------------------
__global__ __launch_bounds__(256) void attn_kernel(float* __restrict__ out)
{
    extern __shared__ float sm[];
    float (*Qs)[PAD] = (float(*)[PAD])(sm);
    float (*Ks)[PAD] = (float(*)[PAD])(sm + 64*PAD);
    float (*Vs)[PAD] = (float(*)[PAD])(sm + 2*64*PAD);
    float (*Ps)[PAD] = (float(*)[PAD])(sm + 3*64*PAD);

    const int b   = blockIdx.y;
    const int m0  = blockIdx.x * 64;
    const int tid = threadIdx.x;
    const int ty  = tid >> 4;           // 0..15 -> rows ty*4..ty*4+3
    const int tx  = tid & 15;           // 0..15 -> cols tx*4..tx*4+3

    const int lrow = tid >> 2;          // 0..63
    const int lc   = (tid & 3) * 16;    // 0,16,32,48

    // Load Q tile
    const float* qb = g_q + (size_t)(b*T_ + m0) * H_;
    #pragma unroll
    for (int i = 0; i < 4; i++) {
        float4 v = *(const float4*)(qb + (size_t)lrow*H_ + lc + i*4);
        *(float4*)&Qs[lrow][lc + i*4] = v;
    }

    float m_i[4], l_i[4], acc[4][4] = {};
    #pragma unroll
    for (int i = 0; i < 4; i++) { m_i[i] = -INFINITY; l_i[i] = 0.0f; }

    const float scale = 0.125f;  // H^-0.5 = 1/8

    for (int n0 = 0; n0 <= m0; n0 += 64) {
        __syncthreads();  // protect K/V/P from previous iteration's readers
        const float* kb = g_k + (size_t)(b*T_ + n0) * H_;
        const float* vb = g_v + (size_t)(b*T_ + n0) * H_;
        #pragma unroll
        for (int i = 0; i < 4; i++) {
            float4 kv = *(const float4*)(kb + (size_t)lrow*H_ + lc + i*4);
            float4 vv = *(const float4*)(vb + (size_t)lrow*H_ + lc + i*4);
            *(float4*)&Ks[lrow][lc + i*4] = kv;
            *(float4*)&Vs[lrow][lc + i*4] = vv;
        }
        __syncthreads();  // also covers initial Q visibility on first iter

        // S = Q K^T (4x4 microtile per thread)
        float s[4][4] = {};
        #pragma unroll 16
        for (int d = 0; d < H_; d++) {
            float a[4], bb[4];
            #pragma unroll
            for (int i = 0; i < 4; i++) a[i]  = Qs[ty*4 + i][d];
            #pragma unroll
            for (int j = 0; j < 4; j++) bb[j] = Ks[tx*4 + j][d];
            #pragma unroll
            for (int i = 0; i < 4; i++)
                #pragma unroll
                for (int j = 0; j < 4; j++)
                    s[i][j] += a[i] * bb[j];
        }

        // scale + causal mask (only ever triggers on the diagonal tile)
        #pragma unroll
        for (int i = 0; i < 4; i++)
            #pragma unroll
            for (int j = 0; j < 4; j++) {
                float sv = s[i][j] * scale;
                if (n0 + tx*4 + j > m0 + ty*4 + i) sv = -INFINITY;
                s[i][j] = sv;
            }

        // Online softmax per row (16 lanes per row share via shfl, width 16)
        #pragma unroll
        for (int i = 0; i < 4; i++) {
            float mx = fmaxf(fmaxf(s[i][0], s[i][1]), fmaxf(s[i][2], s[i][3]));
            mx = fmaxf(mx, __shfl_xor_sync(0xffffffffu, mx, 1, 16));
            mx = fmaxf(mx, __shfl_xor_sync(0xffffffffu, mx, 2, 16));
            mx = fmaxf(mx, __shfl_xor_sync(0xffffffffu, mx, 4, 16));
            mx = fmaxf(mx, __shfl_xor_sync(0xffffffffu, mx, 8, 16));
            float m_new = fmaxf(m_i[i], mx);

            float p0 = __expf(s[i][0] - m_new);
            float p1 = __expf(s[i][1] - m_new);
            float p2 = __expf(s[i][2] - m_new);
            float p3 = __expf(s[i][3] - m_new);
            float rs = (p0 + p1) + (p2 + p3);
            rs += __shfl_xor_sync(0xffffffffu, rs, 1, 16);
            rs += __shfl_xor_sync(0xffffffffu, rs, 2, 16);
            rs += __shfl_xor_sync(0xffffffffu, rs, 4, 16);
            rs += __shfl_xor_sync(0xffffffffu, rs, 8, 16);

            float alpha = __expf(m_i[i] - m_new);
            l_i[i] = l_i[i] * alpha + rs;
            m_i[i] = m_new;
            #pragma unroll
            for (int j = 0; j < 4; j++) acc[i][j] *= alpha;

            Ps[ty*4 + i][tx*4 + 0] = p0;
            Ps[ty*4 + i][tx*4 + 1] = p1;
            Ps[ty*4 + i][tx*4 + 2] = p2;
            Ps[ty*4 + i][tx*4 + 3] = p3;
        }
        __syncthreads();

        // O += P * V  (4x4 microtile)
        #pragma unroll 16
        for (int jj = 0; jj < 64; jj++) {
            float a[4], bb[4];
            #pragma unroll
            for (int i = 0; i < 4; i++) a[i]  = Ps[ty*4 + i][jj];
            #pragma unroll
            for (int j = 0; j < 4; j++) bb[j] = Vs[jj][tx*4 + j];
            #pragma unroll
            for (int i = 0; i < 4; i++)
                #pragma unroll
                for (int j = 0; j < 4; j++)
                    acc[i][j] += a[i] * bb[j];
        }
    }

    // Epilogue: normalize and store
    float* ob = out + (size_t)(b*T_ + m0) * H_;
    #pragma unroll
    for (int i = 0; i < 4; i++) {
        float inv = 1.0f / l_i[i];
        #pragma unroll
        for (int j = 0; j < 4; j++)
            ob[(size_t)(ty*4 + i) * H_ + tx*4 + j] = acc[i][j] * inv;
    }
}

// ---------------------------------------------------------------------------
extern "C" void kernel_launch(void* const* d_in, const int* in_sizes, int n_in,
                              void* d_out, int out_size)
{
    const float* x  = (const float*)d_in[0];
    const float* Wq = (const float*)d_in[1];
    const float* Wk = (const float*)d_in[2];
    const float* Wv = (const float*)d_in[3];
    float* out = (float*)d_out;

    const int attn_smem = 4 * 64 * PAD * sizeof(float);  // 69632 B
    cudaFuncSetAttribute(attn_kernel,
                         cudaFuncAttributeMaxDynamicSharedMemorySize, attn_smem);

    proj_kernel<<<dim3(BT/64, 3), 256>>>(x, Wq, Wk, Wv);
    attn_kernel<<<dim3(T_/64, B_), 256, attn_smem>>>(out);
}

// round 5
// speedup vs baseline: 1.6610x; 1.6610x over previous
#include <cuda_runtime.h>
#include <math.h>

#define B_  4
#define T_  4096
#define C_  1024
#define H_  64
#define BT  (B_*T_)

// Scratch for projected q,k,v (no cudaMalloc allowed)
__device__ float g_q[BT*H_];
__device__ float g_k[BT*H_];
__device__ float g_v[BT*H_];

typedef unsigned long long u64t;
typedef unsigned int u32t;

// ---- packed f32x2 helpers (sm_103a FFMA2 path) ------------------------------
__device__ __forceinline__ u64t pack2(float lo, float hi) {
    u64t r;
    asm("mov.b64 %0, {%1, %2};" : "=l"(r)
        : "r"(__float_as_uint(lo)), "r"(__float_as_uint(hi)));
    return r;
}
__device__ __forceinline__ u64t dup2(float v) { return pack2(v, v); }
__device__ __forceinline__ void unpack2(u64t p, float& lo, float& hi) {
    u32t a, b;
    asm("mov.b64 {%0, %1}, %2;" : "=r"(a), "=r"(b) : "l"(p));
    lo = __uint_as_float(a); hi = __uint_as_float(b);
}
__device__ __forceinline__ u64t fma2(u64t a, u64t b, u64t c) {
    u64t d;
    asm("fma.rn.f32x2 %0, %1, %2, %3;" : "=l"(d) : "l"(a), "l"(b), "l"(c));
    return d;
}
__device__ __forceinline__ u64t mul2(u64t a, u64t b) {
    u64t d;
    asm("mul.rn.f32x2 %0, %1, %2;" : "=l"(d) : "l"(a), "l"(b));
    return d;
}

// ---------------------------------------------------------------------------
// Kernel 1: fused QKV projection. out[row][h] = sum_c x[row][c] * W[h][c]
// grid = (BT/128, 3), block = 256. 128x64 tile, K-chunk 32, f32x2 microkernel.
// smem transposed [k][row] / [k][col] -> conflict-free vector LDS.
// ---------------------------------------------------------------------------
__global__ __launch_bounds__(256) void proj_kernel(
        const float* __restrict__ x,
        const float* __restrict__ Wq,
        const float* __restrict__ Wk,
        const float* __restrict__ Wv)
{
    __shared__ float xt[32][132];   // [k][row], 132 = 128+4 (16B-aligned rows)
    __shared__ float wt[32][68];    // [k][h]

    const float* W; float* outp;
    if (blockIdx.y == 0)      { W = Wq; outp = g_q; }
    else if (blockIdx.y == 1) { W = Wk; outp = g_k; }
    else                      { W = Wv; outp = g_v; }

    const int tid  = threadIdx.x;
    const int ty   = tid >> 4;          // 0..15 -> row-pairs base ty*8
    const int tx   = tid & 15;          // 0..15 -> cols tx*4..+3
    const int rl   = tid >> 3;          // 0..31
    const int c4   = (tid & 7) * 4;     // 0..28
    const int row0 = blockIdx.x * 128;

    u64t acc[4][4] = {};                // [row-pair][col]

    for (int k0 = 0; k0 < C_; k0 += 32) {
        __syncthreads();                // prior-iter readers done
        #pragma unroll
        for (int i = 0; i < 4; i++) {
            int r = rl + 32*i;
            float4 v = *(const float4*)&x[(size_t)(row0 + r)*C_ + k0 + c4];
            xt[c4+0][r] = v.x; xt[c4+1][r] = v.y;
            xt[c4+2][r] = v.z; xt[c4+3][r] = v.w;
        }
        #pragma unroll
        for (int i = 0; i < 2; i++) {
            int h = rl + 32*i;
            float4 v = *(const float4*)&W[(size_t)h*C_ + k0 + c4];
            wt[c4+0][h] = v.x; wt[c4+1][h] = v.y;
            wt[c4+2][h] = v.z; wt[c4+3][h] = v.w;
        }
        __syncthreads();

        #pragma unroll 8
        for (int kk = 0; kk < 32; kk++) {
            ulonglong2 a01 = *(const ulonglong2*)&xt[kk][ty*8];
            ulonglong2 a23 = *(const ulonglong2*)&xt[kk][ty*8 + 4];
            float4 wb = *(const float4*)&wt[kk][tx*4];
            u64t b0 = dup2(wb.x), b1 = dup2(wb.y), b2 = dup2(wb.z), b3 = dup2(wb.w);
            u64t ap[4] = {a01.x, a01.y, a23.x, a23.y};
            #pragma unroll
            for (int ip = 0; ip < 4; ip++) {
                acc[ip][0] = fma2(ap[ip], b0, acc[ip][0]);
                acc[ip][1] = fma2(ap[ip], b1, acc[ip][1]);
                acc[ip][2] = fma2(ap[ip], b2, acc[ip][2]);
                acc[ip][3] = fma2(ap[ip], b3, acc[ip][3]);
            }
        }
    }

    #pragma unroll
    for (int ip = 0; ip < 4; ip++) {
        float lo[4], hi[4];
        #pragma unroll
        for (int j = 0; j < 4; j++) unpack2(acc[ip][j], lo[j], hi[j]);
        size_t r0 = (size_t)(row0 + ty*8 + 2*ip);
        *(float4*)&outp[r0*H_ + tx*4]     = make_float4(lo[0], lo[1], lo[2], lo[3]);
        *(float4*)&outp[(r0+1)*H_ + tx*4] = make_float4(hi[0], hi[1], hi[2], hi[3]);
    }
}

// ---------------------------------------------------------------------------
// Kernel 2: flash-attention, causal, paired for balance.
// grid = (32, B), block = 256. CTA p handles query tiles p and 63-p
// (constant 65 KV-tiles per CTA). Q/K transposed in smem -> conflict-free
// vector LDS; f32x2 packed FMAs for S=QK^T and O=PV.
// Dynamic smem: Qt,Kt,Vs,Ps each [64][68] floats = 69632 bytes.
// ---------------------------------------------------------------------------
__global__ __launch_bounds__(256) void attn_kernel(float* __restrict__ out)
{
    extern __shared__ float sm[];
    float (*Qt)[68] = (float(*)[68])(sm);            // [d][row]
    float (*Kt)[68] = (float(*)[68])(sm + 64*68);    // [d][col]
    float (*Vs)[68] = (float(*)[68])(sm + 2*64*68);  // [s][h]
    float (*Ps)[68] = (float(*)[68])(sm + 3*64*68);  // [row][s]

    const int b    = blockIdx.y;
    const int pr   = blockIdx.x;        // pair index 0..31
    const int tid  = threadIdx.x;
    const int ty   = tid >> 4;          // rows ty*4..+3
    const int tx   = tid & 15;          // cols tx*4..+3
    const int lrow = tid >> 2;          // 0..63
    const int lc   = (tid & 3) * 16;    // 0,16,32,48

    const float scale = 0.125f;         // 64^-0.5

    #pragma unroll 1
    for (int half = 0; half < 2; half++) {
        const int m0 = (half == 0 ? pr : 63 - pr) * 64;

        __syncthreads();                // prior half's readers done
        const float* qb = g_q + (size_t)(b*T_ + m0) * H_;
        #pragma unroll
        for (int i = 0; i < 4; i++) {   // transpose Q into smem
            float4 v = *(const float4*)(qb + (size_t)lrow*H_ + lc + 4*i);
            Qt[lc+4*i+0][lrow] = v.x; Qt[lc+4*i+1][lrow] = v.y;
            Qt[lc+4*i+2][lrow] = v.z; Qt[lc+4*i+3][lrow] = v.w;
        }

        u64t acc[4][2] = {};
        float m_i[4], l_i[4];
        #pragma unroll
        for (int i = 0; i < 4; i++) { m_i[i] = -INFINITY; l_i[i] = 0.0f; }

        for (int n0 = 0; n0 <= m0; n0 += 64) {
            __syncthreads();            // prior tile's readers done (also covers Qt)
            const float* kb = g_k + (size_t)(b*T_ + n0) * H_;
            const float* vb = g_v + (size_t)(b*T_ + n0) * H_;
            #pragma unroll
            for (int i = 0; i < 4; i++) {
                float4 kv = *(const float4*)(kb + (size_t)lrow*H_ + lc + 4*i);
                Kt[lc+4*i+0][lrow] = kv.x; Kt[lc+4*i+1][lrow] = kv.y;
                Kt[lc+4*i+2][lrow] = kv.z; Kt[lc+4*i+3][lrow] = kv.w;
                float4 vv = *(const float4*)(vb + (size_t)lrow*H_ + lc + 4*i);
                *(float4*)&Vs[lrow][lc+4*i] = vv;
            }
            __syncthreads();

            // S = Q K^T, packed along columns
            u64t s2[4][2] = {};
            #pragma unroll 16
            for (int d = 0; d < H_; d++) {
                float4 qa = *(const float4*)&Qt[d][ty*4];
                ulonglong2 kp = *(const ulonglong2*)&Kt[d][tx*4];
                u64t a0 = dup2(qa.x), a1 = dup2(qa.y), a2 = dup2(qa.z), a3 = dup2(qa.w);
                s2[0][0] = fma2(a0, kp.x, s2[0][0]); s2[0][1] = fma2(a0, kp.y, s2[0][1]);
                s2[1][0] = fma2(a1, kp.x, s2[1][0]); s2[1][1] = fma2(a1, kp.y, s2[1][1]);
                s2[2][0] = fma2(a2, kp.x, s2[2][0]); s2[2][1] = fma2(a2, kp.y, s2[2][1]);
                s2[3][0] = fma2(a3, kp.x, s2[3][0]); s2[3][1] = fma2(a3, kp.y, s2[3][1]);
            }

            float s[4][4];
            #pragma unroll
            for (int i = 0; i < 4; i++) {
                unpack2(s2[i][0], s[i][0], s[i][1]);
                unpack2(s2[i][1], s[i][2], s[i][3]);
            }

            if (n0 == m0) {             // diagonal tile: causal mask
                #pragma unroll
                for (int i = 0; i < 4; i++)
                    #pragma unroll
                    for (int j = 0; j < 4; j++)
                        s[i][j] = (tx*4 + j > ty*4 + i) ? -INFINITY : s[i][j] * scale;
            } else {
                #pragma unroll
                for (int i = 0; i < 4; i++)
                    #pragma unroll
                    for (int j = 0; j < 4; j++)
                        s[i][j] *= scale;
            }

            // online softmax per row (16 lanes share a row, width-16 shfl)
            #pragma unroll
            for (int i = 0; i < 4; i++) {
                float mx = fmaxf(fmaxf(s[i][0], s[i][1]), fmaxf(s[i][2], s[i][3]));
                mx = fmaxf(mx, __shfl_xor_sync(0xffffffffu, mx, 1, 16));
                mx = fmaxf(mx, __shfl_xor_sync(0xffffffffu, mx, 2, 16));
                mx = fmaxf(mx, __shfl_xor_sync(0xffffffffu, mx, 4, 16));
                mx = fmaxf(mx, __shfl_xor_sync(0xffffffffu, mx, 8, 16));
                float m_new = fmaxf(m_i[i], mx);

                float p0 = __expf(s[i][0] - m_new);
                float p1 = __expf(s[i][1] - m_new);
                float p2 = __expf(s[i][2] - m_new);
                float p3 = __expf(s[i][3] - m_new);
                float rs = (p0 + p1) + (p2 + p3);
                rs += __shfl_xor_sync(0xffffffffu, rs, 1, 16);
                rs += __shfl_xor_sync(0xffffffffu, rs, 2, 16);
                rs += __shfl_xor_sync(0xffffffffu, rs, 4, 16);
                rs += __shfl_xor_sync(0xffffffffu, rs, 8, 16);

                float alpha = __expf(m_i[i] - m_new);
                l_i[i] = l_i[i] * alpha + rs;
                m_i[i] = m_new;
                u64t al = dup2(alpha);
                acc[i][0] = mul2(acc[i][0], al);
                acc[i][1] = mul2(acc[i][1], al);

                *(float4*)&Ps[ty*4 + i][tx*4] = make_float4(p0, p1, p2, p3);
            }
            __syncthreads();

            // O += P * V, packed along head dim
            #pragma unroll 16
            for (int jj = 0; jj < 64; jj++) {
                ulonglong2 vp = *(const ulonglong2*)&Vs[jj][tx*4];
                u64t a0 = dup2(Ps[ty*4 + 0][jj]);
                u64t a1 = dup2(Ps[ty*4 + 1][jj]);
                u64t a2 = dup2(Ps[ty*4 + 2][jj]);
                u64t a3 = dup2(Ps[ty*4 + 3][jj]);
                acc[0][0] = fma2(a0, vp.x, acc[0][0]); acc[0][1] = fma2(a0, vp.y, acc[0][1]);
                acc[1][0] = fma2(a1, vp.x, acc[1][0]); acc[1][1] = fma2(a1, vp.y, acc[1][1]);
                acc[2][0] = fma2(a2, vp.x, acc[2][0]); acc[2][1] = fma2(a2, vp.y, acc[2][1]);
                acc[3][0] = fma2(a3, vp.x, acc[3][0]); acc[3][1] = fma2(a3, vp.y, acc[3][1]);
            }
        }

        // epilogue: normalize and store (no smem use)
        float* ob = out + (size_t)(b*T_ + m0) * H_;
        #pragma unroll
        for (int i = 0; i < 4; i++) {
            float inv = 1.0f / l_i[i];
            float o0, o1, o2, o3;
            unpack2(acc[i][0], o0, o1);
            unpack2(acc[i][1], o2, o3);
            *(float4*)&ob[(size_t)(ty*4 + i)*H_ + tx*4] =
                make_float4(o0*inv, o1*inv, o2*inv, o3*inv);
        }
    }
}

// ---------------------------------------------------------------------------
extern "C" void kernel_launch(void* const* d_in, const int* in_sizes, int n_in,
                              void* d_out, int out_size)
{
    const float* x  = (const float*)d_in[0];
    const float* Wq = (const float*)d_in[1];
    const float* Wk = (const float*)d_in[2];
    const float* Wv = (const float*)d_in[3];
    float* out = (float*)d_out;

    const int attn_smem = 4 * 64 * 68 * sizeof(float);  // 69632 B
    cudaFuncSetAttribute(attn_kernel,
                         cudaFuncAttributeMaxDynamicSharedMemorySize, attn_smem);

    proj_kernel<<<dim3(BT/128, 3), 256>>>(x, Wq, Wk, Wv);
    attn_kernel<<<dim3(32, B_), 256, attn_smem>>>(out);
}

// round 7
// speedup vs baseline: 4.3078x; 2.5935x over previous
#include <cuda_runtime.h>
#include <cuda_bf16.h>
#include <math.h>

#define B_  4
#define T_  4096
#define C_  1024
#define H_  64
#define BT  (B_*T_)

// Scratch for projected q,k,v (no cudaMalloc allowed)
__device__ float g_q[BT*H_];
__device__ float g_k[BT*H_];
__device__ float g_v[BT*H_];

typedef unsigned long long u64t;
typedef unsigned int u32t;

// ---- helpers ---------------------------------------------------------------
__device__ __forceinline__ u32t smem_u32(const void* p) {
    u32t a;
    asm("{ .reg .u64 t; cvta.to.shared.u64 t, %1; cvt.u32.u64 %0, t; }"
        : "=r"(a) : "l"(p));
    return a;
}

// split two fp32 into bf16-hi pair and bf16-lo pair (packed b32, low half = first)
__device__ __forceinline__ void split_pair(float f0, float f1, u32t& hi, u32t& lo) {
    __nv_bfloat16 h0 = __float2bfloat16(f0);
    __nv_bfloat16 h1 = __float2bfloat16(f1);
    __nv_bfloat16 l0 = __float2bfloat16(f0 - __bfloat162float(h0));
    __nv_bfloat16 l1 = __float2bfloat16(f1 - __bfloat162float(h1));
    hi = (u32t)__bfloat16_as_ushort(h0) | ((u32t)__bfloat16_as_ushort(h1) << 16);
    lo = (u32t)__bfloat16_as_ushort(l0) | ((u32t)__bfloat16_as_ushort(l1) << 16);
}

__device__ __forceinline__ void ldsm_x4(u32t* r, u32t addr) {
    asm volatile("ldmatrix.sync.aligned.m8n8.x4.shared.b16 {%0,%1,%2,%3}, [%4];"
                 : "=r"(r[0]), "=r"(r[1]), "=r"(r[2]), "=r"(r[3]) : "r"(addr));
}
__device__ __forceinline__ void ldsm_x4_t(u32t* r, u32t addr) {
    asm volatile("ldmatrix.sync.aligned.m8n8.x4.trans.shared.b16 {%0,%1,%2,%3}, [%4];"
                 : "=r"(r[0]), "=r"(r[1]), "=r"(r[2]), "=r"(r[3]) : "r"(addr));
}
__device__ __forceinline__ void mma16816(float* d, const u32t* a, u32t b0, u32t b1) {
    asm volatile("mma.sync.aligned.m16n8k16.row.col.f32.bf16.bf16.f32 "
                 "{%0,%1,%2,%3}, {%4,%5,%6,%7}, {%8,%9}, {%0,%1,%2,%3};"
                 : "+f"(d[0]), "+f"(d[1]), "+f"(d[2]), "+f"(d[3])
                 : "r"(a[0]), "r"(a[1]), "r"(a[2]), "r"(a[3]), "r"(b0), "r"(b1));
}

// stage 64 rows x 64 fp32 cols -> bf16 hi/lo smem tiles (row stride 144 B)
// block of 128 threads.
__device__ __forceinline__ void stage64(const float* __restrict__ src,
                                        char* smem, int offHi, int offLo, int tid) {
    const int row = tid >> 1;
    const int c0  = (tid & 1) * 32;
    const float* sp = src + (size_t)row * H_ + c0;
    char* ph = smem + offHi + row * 144 + c0 * 2;
    char* pl = smem + offLo + row * 144 + c0 * 2;
    #pragma unroll
    for (int i = 0; i < 8; i++) {
        float4 v = *(const float4*)(sp + 4*i);
        u32t h0, l0, h1, l1;
        split_pair(v.x, v.y, h0, l0);
        split_pair(v.z, v.w, h1, l1);
        *(u32t*)(ph + 8*i)     = h0; *(u32t*)(ph + 8*i + 4) = h1;
        *(u32t*)(pl + 8*i)     = l0; *(u32t*)(pl + 8*i + 4) = l1;
    }
}

// ---------------------------------------------------------------------------
// Kernel 1: QKV projection via bf16 split-precision HMMA.
// grid = BT/128, block = 256 (8 warps x 16 rows). N = 192 (3 x 64), KC = 32.
// smem rows padded to 40 bf16 (80 B) -> conflict-free ldmatrix.
// ---------------------------------------------------------------------------
#define PXH 0
#define PXL 10240
#define PWH 20480
#define PWL 35840
#define PROJ_SMEM 51200

__global__ __launch_bounds__(256) void proj_tc_kernel(
        const float* __restrict__ x,
        const float* __restrict__ Wq,
        const float* __restrict__ Wk,
        const float* __restrict__ Wv)
{
    extern __shared__ char smem[];
    const u32t sb = smem_u32(smem);
    const int tid  = threadIdx.x;
    const int wid  = tid >> 5;
    const int lane = tid & 31;
    const int row0 = blockIdx.x * 128;
    const float* Ws[3] = {Wq, Wk, Wv};

    float acc[24][4] = {};   // 24 n-tiles (8 per W matrix)

    // ldmatrix lane addressing
    const int a_row = (lane & 15);
    const int a_c8  = ((lane >> 4) & 1) * 8;
    const int b_row = (lane & 7) + ((lane >> 4) & 1) * 8;
    const int b_c8  = ((lane >> 3) & 1) * 8;

    for (int ch = 0; ch < 32; ch++) {
        const int k0 = ch * 32;
        __syncthreads();
        // stage x chunk: 128 rows x 32 cols
        #pragma unroll
        for (int i = 0; i < 4; i++) {
            int f4 = tid + 256*i;
            int r  = f4 >> 3, c4 = (f4 & 7) * 4;
            float4 v = *(const float4*)&x[(size_t)(row0 + r)*C_ + k0 + c4];
            u32t h0, l0, h1, l1;
            split_pair(v.x, v.y, h0, l0);
            split_pair(v.z, v.w, h1, l1);
            char* ph = smem + PXH + r*80 + c4*2;
            char* pl = smem + PXL + r*80 + c4*2;
            *(u32t*)ph = h0; *(u32t*)(ph+4) = h1;
            *(u32t*)pl = l0; *(u32t*)(pl+4) = l1;
        }
        // stage W chunk: 192 rows x 32 cols
        #pragma unroll
        for (int i = 0; i < 6; i++) {
            int f4 = tid + 256*i;
            int r  = f4 >> 3, c4 = (f4 & 7) * 4;
            const float* wp = Ws[r >> 6] + (size_t)(r & 63)*C_ + k0 + c4;
            float4 v = *(const float4*)wp;
            u32t h0, l0, h1, l1;
            split_pair(v.x, v.y, h0, l0);
            split_pair(v.z, v.w, h1, l1);
            char* ph = smem + PWH + r*80 + c4*2;
            char* pl = smem + PWL + r*80 + c4*2;
            *(u32t*)ph = h0; *(u32t*)(ph+4) = h1;
            *(u32t*)pl = l0; *(u32t*)(pl+4) = l1;
        }
        __syncthreads();

        u32t xh[2][4], xl[2][4];
        #pragma unroll
        for (int s = 0; s < 2; s++) {
            u32t ab = (u32t)((16*wid + a_row)*80 + (a_c8 + 16*s)*2);
            ldsm_x4(xh[s], sb + PXH + ab);
            ldsm_x4(xl[s], sb + PXL + ab);
        }
        #pragma unroll
        for (int jp = 0; jp < 12; jp++) {
            #pragma unroll
            for (int s = 0; s < 2; s++) {
                u32t bb = (u32t)((16*jp + b_row)*80 + (b_c8 + 16*s)*2);
                u32t bh[4], bl[4];
                ldsm_x4(bh, sb + PWH + bb);
                ldsm_x4(bl, sb + PWL + bb);
                mma16816(acc[2*jp],   xh[s], bh[0], bh[1]);
                mma16816(acc[2*jp],   xh[s], bl[0], bl[1]);
                mma16816(acc[2*jp],   xl[s], bh[0], bh[1]);
                mma16816(acc[2*jp+1], xh[s], bh[2], bh[3]);
                mma16816(acc[2*jp+1], xh[s], bl[2], bl[3]);
                mma16816(acc[2*jp+1], xl[s], bh[2], bh[3]);
            }
        }
    }

    // epilogue
    const int q = lane & 3, r = lane >> 2;
    float* outs[3] = {g_q, g_k, g_v};
    #pragma unroll
    for (int t = 0; t < 24; t++) {
        float* op = outs[t >> 3];
        int col = (t & 7)*8 + 2*q;
        size_t rw = (size_t)(row0 + 16*wid + r);
        *(float2*)&op[rw*H_ + col]       = make_float2(acc[t][0], acc[t][1]);
        *(float2*)&op[(rw + 8)*H_ + col] = make_float2(acc[t][2], acc[t][3]);
    }
}

// ---------------------------------------------------------------------------
// Kernel 2: flash-attention via bf16 split-precision HMMA, causal, paired.
// grid = (32, B), block = 128 (4 warps x 16 rows). BM = BN = 64.
// K smem [n][d], V smem [s][h] (trans-ldmatrix), rows padded to 72 bf16.
// P stays in registers (S C-frags repacked as PV A-frags).
// ---------------------------------------------------------------------------
#define AKH 0
#define AKL 9216
#define AVH 18432
#define AVL 27648
#define ATTN_SMEM 36864

__global__ __launch_bounds__(128) void attn_tc_kernel(float* __restrict__ out)
{
    extern __shared__ char smem[];
    const u32t sb = smem_u32(smem);
    const int tid  = threadIdx.x;
    const int wid  = tid >> 5;
    const int lane = tid & 31;
    const int b    = blockIdx.y;
    const int pr   = blockIdx.x;
    const int q    = lane & 3;
    const int r    = lane >> 2;

    const int a_row = (lane & 15);
    const int a_c8  = ((lane >> 4) & 1) * 8;
    const int b_row = (lane & 7) + ((lane >> 4) & 1) * 8;   // K frags
    const int b_c8  = ((lane >> 3) & 1) * 8;
    const int v_row = (lane & 7) + ((lane >> 3) & 1) * 8;   // V trans frags
    const int v_c8  = ((lane >> 4) & 1) * 8;

    const float scale = 0.125f;

    #pragma unroll 1
    for (int half = 0; half < 2; half++) {
        const int m0 = (half == 0 ? pr : 63 - pr) * 64;

        __syncthreads();
        stage64(g_q + (size_t)(b*T_ + m0)*H_, smem, AKH, AKL, tid);
        __syncthreads();

        u32t qh[4][4], ql[4][4];
        #pragma unroll
        for (int s = 0; s < 4; s++) {
            u32t ab = (u32t)((16*wid + a_row)*144 + (a_c8 + 16*s)*2);
            ldsm_x4(qh[s], sb + AKH + ab);
            ldsm_x4(ql[s], sb + AKL + ab);
        }

        float o[8][4] = {};
        float m_i0 = -INFINITY, m_i1 = -INFINITY, l_i0 = 0.f, l_i1 = 0.f;
        const int row0g = m0 + 16*wid + r;
        const int row1g = row0g + 8;

        for (int n0 = 0; n0 <= m0; n0 += 64) {
            __syncthreads();   // Q frags read / prev tile consumed
            stage64(g_k + (size_t)(b*T_ + n0)*H_, smem, AKH, AKL, tid);
            stage64(g_v + (size_t)(b*T_ + n0)*H_, smem, AVH, AVL, tid);
            __syncthreads();

            // ---- S = Q K^T ----
            float sf[8][4] = {};
            #pragma unroll
            for (int jp = 0; jp < 4; jp++) {
                #pragma unroll
                for (int s = 0; s < 4; s++) {
                    u32t bb = (u32t)((16*jp + b_row)*144 + (b_c8 + 16*s)*2);
                    u32t bh[4], bl[4];
                    ldsm_x4(bh, sb + AKH + bb);
                    ldsm_x4(bl, sb + AKL + bb);
                    mma16816(sf[2*jp],   qh[s], bh[0], bh[1]);
                    mma16816(sf[2*jp],   qh[s], bl[0], bl[1]);
                    mma16816(sf[2*jp],   ql[s], bh[0], bh[1]);
                    mma16816(sf[2*jp+1], qh[s], bh[2], bh[3]);
                    mma16816(sf[2*jp+1], qh[s], bl[2], bl[3]);
                    mma16816(sf[2*jp+1], ql[s], bh[2], bh[3]);
                }
            }

            // ---- scale + causal mask ----
            if (n0 == m0) {
                #pragma unroll
                for (int j = 0; j < 8; j++) {
                    int c = n0 + 8*j + 2*q;
                    sf[j][0] = (c   > row0g) ? -INFINITY : sf[j][0]*scale;
                    sf[j][1] = (c+1 > row0g) ? -INFINITY : sf[j][1]*scale;
                    sf[j][2] = (c   > row1g) ? -INFINITY : sf[j][2]*scale;
                    sf[j][3] = (c+1 > row1g) ? -INFINITY : sf[j][3]*scale;
                }
            } else {
                #pragma unroll
                for (int j = 0; j < 8; j++)
                    #pragma unroll
                    for (int e = 0; e < 4; e++) sf[j][e] *= scale;
            }

            // ---- online softmax (rows r and r+8, quad-shuffle reductions) ----
            float mx0 = -INFINITY, mx1 = -INFINITY;
            #pragma unroll
            for (int j = 0; j < 8; j++) {
                mx0 = fmaxf(mx0, fmaxf(sf[j][0], sf[j][1]));
                mx1 = fmaxf(mx1, fmaxf(sf[j][2], sf[j][3]));
            }
            mx0 = fmaxf(mx0, __shfl_xor_sync(0xffffffffu, mx0, 1));
            mx0 = fmaxf(mx0, __shfl_xor_sync(0xffffffffu, mx0, 2));
            mx1 = fmaxf(mx1, __shfl_xor_sync(0xffffffffu, mx1, 1));
            mx1 = fmaxf(mx1, __shfl_xor_sync(0xffffffffu, mx1, 2));
            float mn0 = fmaxf(m_i0, mx0);
            float mn1 = fmaxf(m_i1, mx1);
            float al0 = __expf(m_i0 - mn0);
            float al1 = __expf(m_i1 - mn1);

            float rs0 = 0.f, rs1 = 0.f;
            u32t pah[4][4], pal[4][4];   // PV A-frags (k-step t0)
            #pragma unroll
            for (int j = 0; j < 8; j++) {
                float p0 = __expf(sf[j][0] - mn0);
                float p1 = __expf(sf[j][1] - mn0);
                float p2 = __expf(sf[j][2] - mn1);
                float p3 = __expf(sf[j][3] - mn1);
                rs0 += p0 + p1; rs1 += p2 + p3;
                int t0 = j >> 1, hi2 = (j & 1) * 2;
                split_pair(p0, p1, pah[t0][hi2],   pal[t0][hi2]);
                split_pair(p2, p3, pah[t0][hi2+1], pal[t0][hi2+1]);
            }
            rs0 += __shfl_xor_sync(0xffffffffu, rs0, 1);
            rs0 += __shfl_xor_sync(0xffffffffu, rs0, 2);
            rs1 += __shfl_xor_sync(0xffffffffu, rs1, 1);
            rs1 += __shfl_xor_sync(0xffffffffu, rs1, 2);
            l_i0 = l_i0*al0 + rs0;  m_i0 = mn0;
            l_i1 = l_i1*al1 + rs1;  m_i1 = mn1;
            #pragma unroll
            for (int j = 0; j < 8; j++) {
                o[j][0] *= al0; o[j][1] *= al0;
                o[j][2] *= al1; o[j][3] *= al1;
            }

            // ---- O += P V ----
            #pragma unroll
            for (int jp = 0; jp < 4; jp++) {
                #pragma unroll
                for (int t0 = 0; t0 < 4; t0++) {
                    u32t vb = (u32t)((16*t0 + v_row)*144 + (16*jp + v_c8)*2);
                    u32t vh[4], vl[4];
                    ldsm_x4_t(vh, sb + AVH + vb);
                    ldsm_x4_t(vl, sb + AVL + vb);
                    mma16816(o[2*jp],   pah[t0], vh[0], vh[1]);
                    mma16816(o[2*jp],   pah[t0], vl[0], vl[1]);
                    mma16816(o[2*jp],   pal[t0], vh[0], vh[1]);
                    mma16816(o[2*jp+1], pah[t0], vh[2], vh[3]);
                    mma16816(o[2*jp+1], pah[t0], vl[2], vl[3]);
                    mma16816(o[2*jp+1], pal[t0], vh[2], vh[3]);
                }
            }
        }

        // ---- epilogue ----
        float inv0 = 1.0f / l_i0;
        float inv1 = 1.0f / l_i1;
        float* ob = out + (size_t)(b*T_) * H_;
        #pragma unroll
        for (int j = 0; j < 8; j++) {
            int col = 8*j + 2*q;
            *(float2*)&ob[(size_t)row0g*H_ + col] =
                make_float2(o[j][0]*inv0, o[j][1]*inv0);
            *(float2*)&ob[(size_t)row1g*H_ + col] =
                make_float2(o[j][2]*inv1, o[j][3]*inv1);
        }
    }
}

// ---------------------------------------------------------------------------
extern "C" void kernel_launch(void* const* d_in, const int* in_sizes, int n_in,
                              void* d_out, int out_size)
{
    const float* x  = (const float*)d_in[0];
    const float* Wq = (const float*)d_in[1];
    const float* Wk = (const float*)d_in[2];
    const float* Wv = (const float*)d_in[3];
    float* out = (float*)d_out;

    cudaFuncSetAttribute(proj_tc_kernel,
                         cudaFuncAttributeMaxDynamicSharedMemorySize, PROJ_SMEM);
    cudaFuncSetAttribute(attn_tc_kernel,
                         cudaFuncAttributeMaxDynamicSharedMemorySize, ATTN_SMEM);

    proj_tc_kernel<<<BT/128, 256, PROJ_SMEM>>>(x, Wq, Wk, Wv);
    attn_tc_kernel<<<dim3(32, B_), 128, ATTN_SMEM>>>(out);
}

// round 8
// speedup vs baseline: 5.0349x; 1.1688x over previous
#include <cuda_runtime.h>
#include <cuda_bf16.h>
#include <math.h>

#define B_  4
#define T_  4096
#define C_  1024
#define H_  64
#define BT  (B_*T_)

// Scratch for projected q,k,v (no cudaMalloc allowed)
__device__ float g_q[BT*H_];
__device__ float g_k[BT*H_];
__device__ float g_v[BT*H_];

typedef unsigned int u32t;

// ---- helpers ---------------------------------------------------------------
__device__ __forceinline__ u32t smem_u32(const void* p) {
    u32t a;
    asm("{ .reg .u64 t; cvta.to.shared.u64 t, %1; cvt.u32.u64 %0, t; }"
        : "=r"(a) : "l"(p));
    return a;
}

__device__ __forceinline__ void split_pair(float f0, float f1, u32t& hi, u32t& lo) {
    __nv_bfloat16 h0 = __float2bfloat16(f0);
    __nv_bfloat16 h1 = __float2bfloat16(f1);
    __nv_bfloat16 l0 = __float2bfloat16(f0 - __bfloat162float(h0));
    __nv_bfloat16 l1 = __float2bfloat16(f1 - __bfloat162float(h1));
    hi = (u32t)__bfloat16_as_ushort(h0) | ((u32t)__bfloat16_as_ushort(h1) << 16);
    lo = (u32t)__bfloat16_as_ushort(l0) | ((u32t)__bfloat16_as_ushort(l1) << 16);
}

__device__ __forceinline__ void ldsm_x4(u32t* r, u32t addr) {
    asm volatile("ldmatrix.sync.aligned.m8n8.x4.shared.b16 {%0,%1,%2,%3}, [%4];"
                 : "=r"(r[0]), "=r"(r[1]), "=r"(r[2]), "=r"(r[3]) : "r"(addr));
}
__device__ __forceinline__ void ldsm_x4_t(u32t* r, u32t addr) {
    asm volatile("ldmatrix.sync.aligned.m8n8.x4.trans.shared.b16 {%0,%1,%2,%3}, [%4];"
                 : "=r"(r[0]), "=r"(r[1]), "=r"(r[2]), "=r"(r[3]) : "r"(addr));
}
__device__ __forceinline__ void mma16816(float* d, const u32t* a, u32t b0, u32t b1) {
    asm volatile("mma.sync.aligned.m16n8k16.row.col.f32.bf16.bf16.f32 "
                 "{%0,%1,%2,%3}, {%4,%5,%6,%7}, {%8,%9}, {%0,%1,%2,%3};"
                 : "+f"(d[0]), "+f"(d[1]), "+f"(d[2]), "+f"(d[3])
                 : "r"(a[0]), "r"(a[1]), "r"(a[2]), "r"(a[3]), "r"(b0), "r"(b1));
}

// stage 64 rows x 64 fp32 cols -> bf16 hi/lo smem tiles (row stride 144 B)
// 128 threads (pass group-local tid).
__device__ __forceinline__ void stage64(const float* __restrict__ src,
                                        char* smem, int offHi, int offLo, int tid) {
    const int row = tid >> 1;
    const int c0  = (tid & 1) * 32;
    const float* sp = src + (size_t)row * H_ + c0;
    char* ph = smem + offHi + row * 144 + c0 * 2;
    char* pl = smem + offLo + row * 144 + c0 * 2;
    #pragma unroll
    for (int i = 0; i < 8; i++) {
        float4 v = *(const float4*)(sp + 4*i);
        u32t h0, l0, h1, l1;
        split_pair(v.x, v.y, h0, l0);
        split_pair(v.z, v.w, h1, l1);
        *(u32t*)(ph + 8*i)     = h0; *(u32t*)(ph + 8*i + 4) = h1;
        *(u32t*)(pl + 8*i)     = l0; *(u32t*)(pl + 8*i + 4) = l1;
    }
}

// ---------------------------------------------------------------------------
// Kernel 1: QKV projection via bf16 split-precision HMMA, pipelined staging.
// grid = BT/128, block = 256 (8 warps x 16 rows). N = 192 (3 x 64), KC = 32.
// ---------------------------------------------------------------------------
#define PXH 0
#define PXL 10240
#define PWH 20480
#define PWL 35840
#define PROJ_SMEM 51200

__global__ __launch_bounds__(256) void proj_tc_kernel(
        const float* __restrict__ x,
        const float* __restrict__ Wq,
        const float* __restrict__ Wk,
        const float* __restrict__ Wv)
{
    extern __shared__ char smem[];
    const u32t sb = smem_u32(smem);
    const int tid  = threadIdx.x;
    const int wid  = tid >> 5;
    const int lane = tid & 31;
    const int row0 = blockIdx.x * 128;
    const float* Ws[3] = {Wq, Wk, Wv};

    float acc[24][4] = {};

    const int a_row = (lane & 15);
    const int a_c8  = ((lane >> 4) & 1) * 8;
    const int b_row = (lane & 7) + ((lane >> 4) & 1) * 8;
    const int b_c8  = ((lane >> 3) & 1) * 8;

    // prefetch registers
    float4 vx[4], vw[6];
    {
        #pragma unroll
        for (int i = 0; i < 4; i++) {
            int f4 = tid + 256*i; int r = f4 >> 3, c4 = (f4 & 7) * 4;
            vx[i] = *(const float4*)&x[(size_t)(row0 + r)*C_ + c4];
        }
        #pragma unroll
        for (int i = 0; i < 6; i++) {
            int f4 = tid + 256*i; int r = f4 >> 3, c4 = (f4 & 7) * 4;
            vw[i] = *(const float4*)(Ws[r >> 6] + (size_t)(r & 63)*C_ + c4);
        }
    }

    for (int ch = 0; ch < 32; ch++) {
        // store prefetched chunk to smem (split hi/lo)
        #pragma unroll
        for (int i = 0; i < 4; i++) {
            int f4 = tid + 256*i; int r = f4 >> 3, c4 = (f4 & 7) * 4;
            u32t h0, l0, h1, l1;
            split_pair(vx[i].x, vx[i].y, h0, l0);
            split_pair(vx[i].z, vx[i].w, h1, l1);
            char* ph = smem + PXH + r*80 + c4*2;
            char* pl = smem + PXL + r*80 + c4*2;
            *(u32t*)ph = h0; *(u32t*)(ph+4) = h1;
            *(u32t*)pl = l0; *(u32t*)(pl+4) = l1;
        }
        #pragma unroll
        for (int i = 0; i < 6; i++) {
            int f4 = tid + 256*i; int r = f4 >> 3, c4 = (f4 & 7) * 4;
            u32t h0, l0, h1, l1;
            split_pair(vw[i].x, vw[i].y, h0, l0);
            split_pair(vw[i].z, vw[i].w, h1, l1);
            char* ph = smem + PWH + r*80 + c4*2;
            char* pl = smem + PWL + r*80 + c4*2;
            *(u32t*)ph = h0; *(u32t*)(ph+4) = h1;
            *(u32t*)pl = l0; *(u32t*)(pl+4) = l1;
        }
        __syncthreads();

        // issue next chunk's global loads (consumed next iteration)
        if (ch < 31) {
            const int k0n = (ch + 1) * 32;
            #pragma unroll
            for (int i = 0; i < 4; i++) {
                int f4 = tid + 256*i; int r = f4 >> 3, c4 = (f4 & 7) * 4;
                vx[i] = *(const float4*)&x[(size_t)(row0 + r)*C_ + k0n + c4];
            }
            #pragma unroll
            for (int i = 0; i < 6; i++) {
                int f4 = tid + 256*i; int r = f4 >> 3, c4 = (f4 & 7) * 4;
                vw[i] = *(const float4*)(Ws[r >> 6] + (size_t)(r & 63)*C_ + k0n + c4);
            }
        }

        u32t xh[2][4], xl[2][4];
        #pragma unroll
        for (int s = 0; s < 2; s++) {
            u32t ab = (u32t)((16*wid + a_row)*80 + (a_c8 + 16*s)*2);
            ldsm_x4(xh[s], sb + PXH + ab);
            ldsm_x4(xl[s], sb + PXL + ab);
        }
        #pragma unroll
        for (int jp = 0; jp < 12; jp++) {
            #pragma unroll
            for (int s = 0; s < 2; s++) {
                u32t bb = (u32t)((16*jp + b_row)*80 + (b_c8 + 16*s)*2);
                u32t bh[4], bl[4];
                ldsm_x4(bh, sb + PWH + bb);
                ldsm_x4(bl, sb + PWL + bb);
                mma16816(acc[2*jp],   xh[s], bh[0], bh[1]);
                mma16816(acc[2*jp],   xh[s], bl[0], bl[1]);
                mma16816(acc[2*jp],   xl[s], bh[0], bh[1]);
                mma16816(acc[2*jp+1], xh[s], bh[2], bh[3]);
                mma16816(acc[2*jp+1], xh[s], bl[2], bl[3]);
                mma16816(acc[2*jp+1], xl[s], bh[2], bh[3]);
            }
        }
        __syncthreads();
    }

    const int q = lane & 3, r = lane >> 2;
    float* outs[3] = {g_q, g_k, g_v};
    #pragma unroll
    for (int t = 0; t < 24; t++) {
        float* op = outs[t >> 3];
        int col = (t & 7)*8 + 2*q;
        size_t rw = (size_t)(row0 + 16*wid + r);
        *(float2*)&op[rw*H_ + col]       = make_float2(acc[t][0], acc[t][1]);
        *(float2*)&op[(rw + 8)*H_ + col] = make_float2(acc[t][2], acc[t][3]);
    }
}

// ---------------------------------------------------------------------------
// Kernel 2: flash-attention, bf16 split HMMA, causal, paired, split-KV.
// grid = (32, B), block = 256 = 2 warpgroups of 4 warps.
// CTA handles query pair {pr, 63-pr}; per query tile the KV range is split
// evenly between the two groups (private smem, named barriers), partials
// merged via (m,l,O) softmax-merge through smem.
// ---------------------------------------------------------------------------
#define AKH 0
#define AKL 9216
#define AVH 18432
#define AVL 27648
#define GRP_BYTES 36864
#define ATTN_SMEM (2*GRP_BYTES)

__global__ __launch_bounds__(256) void attn_tc_kernel(float* __restrict__ out)
{
    extern __shared__ char smem[];
    const int tid  = threadIdx.x;
    const int g    = tid >> 7;          // warpgroup 0/1
    const int ltid = tid & 127;
    const int wid  = ltid >> 5;
    const int lane = tid & 31;
    const int b    = blockIdx.y;
    const int pr   = blockIdx.x;
    const int q    = lane & 3;
    const int r    = lane >> 2;

    char* gsm = smem + g * GRP_BYTES;
    const u32t sbg = smem_u32(gsm);

    const int a_row = (lane & 15);
    const int a_c8  = ((lane >> 4) & 1) * 8;
    const int b_row = (lane & 7) + ((lane >> 4) & 1) * 8;
    const int b_c8  = ((lane >> 3) & 1) * 8;
    const int v_row = (lane & 7) + ((lane >> 3) & 1) * 8;
    const int v_c8  = ((lane >> 4) & 1) * 8;

    const float scale = 0.125f;

    float* MD = (float*)(smem + GRP_BYTES);          // 128*4 floats (merge m/l)
    float* OD = (float*)(smem + GRP_BYTES + 2048);   // 128*32 floats (merge O)

    #pragma unroll 1
    for (int half = 0; half < 2; half++) {
        const int m0 = (half == 0 ? pr : 63 - pr) * 64;
        const int nt = m0/64 + 1;
        const int hsp = (nt + 1) >> 1;
        const int tb = g ? hsp : 0;
        const int te = g ? nt  : hsp;

        asm volatile("bar.sync %0, 128;" :: "r"(g+1) : "memory");
        stage64(g_q + (size_t)(b*T_ + m0)*H_, gsm, AKH, AKL, ltid);
        asm volatile("bar.sync %0, 128;" :: "r"(g+1) : "memory");

        u32t qh[4][4], ql[4][4];
        #pragma unroll
        for (int s = 0; s < 4; s++) {
            u32t ab = (u32t)((16*wid + a_row)*144 + (a_c8 + 16*s)*2);
            ldsm_x4(qh[s], sbg + AKH + ab);
            ldsm_x4(ql[s], sbg + AKL + ab);
        }

        float o[8][4] = {};
        float m_i0 = -INFINITY, m_i1 = -INFINITY, l_i0 = 0.f, l_i1 = 0.f;
        const int row0g = m0 + 16*wid + r;
        const int row1g = row0g + 8;

        for (int t = tb; t < te; t++) {
            const int n0 = t * 64;
            asm volatile("bar.sync %0, 128;" :: "r"(g+1) : "memory");
            stage64(g_k + (size_t)(b*T_ + n0)*H_, gsm, AKH, AKL, ltid);
            stage64(g_v + (size_t)(b*T_ + n0)*H_, gsm, AVH, AVL, ltid);
            asm volatile("bar.sync %0, 128;" :: "r"(g+1) : "memory");

            // ---- S = Q K^T ----
            float sf[8][4] = {};
            #pragma unroll
            for (int jp = 0; jp < 4; jp++) {
                #pragma unroll
                for (int s = 0; s < 4; s++) {
                    u32t bb = (u32t)((16*jp + b_row)*144 + (b_c8 + 16*s)*2);
                    u32t bh[4], bl[4];
                    ldsm_x4(bh, sbg + AKH + bb);
                    ldsm_x4(bl, sbg + AKL + bb);
                    mma16816(sf[2*jp],   qh[s], bh[0], bh[1]);
                    mma16816(sf[2*jp],   qh[s], bl[0], bl[1]);
                    mma16816(sf[2*jp],   ql[s], bh[0], bh[1]);
                    mma16816(sf[2*jp+1], qh[s], bh[2], bh[3]);
                    mma16816(sf[2*jp+1], qh[s], bl[2], bl[3]);
                    mma16816(sf[2*jp+1], ql[s], bh[2], bh[3]);
                }
            }

            // ---- scale + causal mask ----
            if (n0 == m0) {
                #pragma unroll
                for (int j = 0; j < 8; j++) {
                    int c = n0 + 8*j + 2*q;
                    sf[j][0] = (c   > row0g) ? -INFINITY : sf[j][0]*scale;
                    sf[j][1] = (c+1 > row0g) ? -INFINITY : sf[j][1]*scale;
                    sf[j][2] = (c   > row1g) ? -INFINITY : sf[j][2]*scale;
                    sf[j][3] = (c+1 > row1g) ? -INFINITY : sf[j][3]*scale;
                }
            } else {
                #pragma unroll
                for (int j = 0; j < 8; j++)
                    #pragma unroll
                    for (int e = 0; e < 4; e++) sf[j][e] *= scale;
            }

            // ---- online softmax ----
            float mx0 = -INFINITY, mx1 = -INFINITY;
            #pragma unroll
            for (int j = 0; j < 8; j++) {
                mx0 = fmaxf(mx0, fmaxf(sf[j][0], sf[j][1]));
                mx1 = fmaxf(mx1, fmaxf(sf[j][2], sf[j][3]));
            }
            mx0 = fmaxf(mx0, __shfl_xor_sync(0xffffffffu, mx0, 1));
            mx0 = fmaxf(mx0, __shfl_xor_sync(0xffffffffu, mx0, 2));
            mx1 = fmaxf(mx1, __shfl_xor_sync(0xffffffffu, mx1, 1));
            mx1 = fmaxf(mx1, __shfl_xor_sync(0xffffffffu, mx1, 2));
            float mn0 = fmaxf(m_i0, mx0);
            float mn1 = fmaxf(m_i1, mx1);
            float al0 = __expf(m_i0 - mn0);
            float al1 = __expf(m_i1 - mn1);

            float rs0 = 0.f, rs1 = 0.f;
            u32t pah[4][4], pal[4][4];
            #pragma unroll
            for (int j = 0; j < 8; j++) {
                float p0 = __expf(sf[j][0] - mn0);
                float p1 = __expf(sf[j][1] - mn0);
                float p2 = __expf(sf[j][2] - mn1);
                float p3 = __expf(sf[j][3] - mn1);
                rs0 += p0 + p1; rs1 += p2 + p3;
                int t0 = j >> 1, hi2 = (j & 1) * 2;
                split_pair(p0, p1, pah[t0][hi2],   pal[t0][hi2]);
                split_pair(p2, p3, pah[t0][hi2+1], pal[t0][hi2+1]);
            }
            rs0 += __shfl_xor_sync(0xffffffffu, rs0, 1);
            rs0 += __shfl_xor_sync(0xffffffffu, rs0, 2);
            rs1 += __shfl_xor_sync(0xffffffffu, rs1, 1);
            rs1 += __shfl_xor_sync(0xffffffffu, rs1, 2);
            l_i0 = l_i0*al0 + rs0;  m_i0 = mn0;
            l_i1 = l_i1*al1 + rs1;  m_i1 = mn1;
            #pragma unroll
            for (int j = 0; j < 8; j++) {
                o[j][0] *= al0; o[j][1] *= al0;
                o[j][2] *= al1; o[j][3] *= al1;
            }

            // ---- O += P V ----
            #pragma unroll
            for (int jp = 0; jp < 4; jp++) {
                #pragma unroll
                for (int t0 = 0; t0 < 4; t0++) {
                    u32t vb = (u32t)((16*t0 + v_row)*144 + (16*jp + v_c8)*2);
                    u32t vh[4], vl[4];
                    ldsm_x4_t(vh, sbg + AVH + vb);
                    ldsm_x4_t(vl, sbg + AVL + vb);
                    mma16816(o[2*jp],   pah[t0], vh[0], vh[1]);
                    mma16816(o[2*jp],   pah[t0], vl[0], vl[1]);
                    mma16816(o[2*jp],   pal[t0], vh[0], vh[1]);
                    mma16816(o[2*jp+1], pah[t0], vh[2], vh[3]);
                    mma16816(o[2*jp+1], pah[t0], vl[2], vl[3]);
                    mma16816(o[2*jp+1], pal[t0], vh[2], vh[3]);
                }
            }
        }

        // ---- merge partials across the two groups ----
        if (g == 1) {
            MD[ltid*4+0] = m_i0; MD[ltid*4+1] = m_i1;
            MD[ltid*4+2] = l_i0; MD[ltid*4+3] = l_i1;
            #pragma unroll
            for (int j = 0; j < 8; j++)
                #pragma unroll
                for (int e = 0; e < 4; e++)
                    OD[ltid*32 + j*4 + e] = o[j][e];
        }
        __syncthreads();
        if (g == 0) {
            float m1_0 = MD[ltid*4+0], m1_1 = MD[ltid*4+1];
            float l1_0 = MD[ltid*4+2], l1_1 = MD[ltid*4+3];
            float mn0 = fmaxf(m_i0, m1_0);
            float mn1 = fmaxf(m_i1, m1_1);
            float a0 = __expf(m_i0 - mn0), b0 = __expf(m1_0 - mn0);
            float a1 = __expf(m_i1 - mn1), b1 = __expf(m1_1 - mn1);
            float lt0 = l_i0*a0 + l1_0*b0;
            float lt1 = l_i1*a1 + l1_1*b1;
            float inv0 = 1.0f / lt0;
            float inv1 = 1.0f / lt1;
            float* ob = out + (size_t)(b*T_) * H_;
            #pragma unroll
            for (int j = 0; j < 8; j++) {
                int col = 8*j + 2*q;
                float o0 = (o[j][0]*a0 + OD[ltid*32 + j*4 + 0]*b0) * inv0;
                float o1 = (o[j][1]*a0 + OD[ltid*32 + j*4 + 1]*b0) * inv0;
                float o2 = (o[j][2]*a1 + OD[ltid*32 + j*4 + 2]*b1) * inv1;
                float o3 = (o[j][3]*a1 + OD[ltid*32 + j*4 + 3]*b1) * inv1;
                *(float2*)&ob[(size_t)row0g*H_ + col] = make_float2(o0, o1);
                *(float2*)&ob[(size_t)row1g*H_ + col] = make_float2(o2, o3);
            }
        }
        __syncthreads();
    }
}

// ---------------------------------------------------------------------------
extern "C" void kernel_launch(void* const* d_in, const int* in_sizes, int n_in,
                              void* d_out, int out_size)
{
    const float* x  = (const float*)d_in[0];
    const float* Wq = (const float*)d_in[1];
    const float* Wk = (const float*)d_in[2];
    const float* Wv = (const float*)d_in[3];
    float* out = (float*)d_out;

    cudaFuncSetAttribute(proj_tc_kernel,
                         cudaFuncAttributeMaxDynamicSharedMemorySize, PROJ_SMEM);
    cudaFuncSetAttribute(attn_tc_kernel,
                         cudaFuncAttributeMaxDynamicSharedMemorySize, ATTN_SMEM);

    proj_tc_kernel<<<BT/128, 256, PROJ_SMEM>>>(x, Wq, Wk, Wv);
    attn_tc_kernel<<<dim3(32, B_), 256, ATTN_SMEM>>>(out);
}

// round 10
// speedup vs baseline: 6.9138x; 1.3732x over previous
#include <cuda_runtime.h>
#include <cuda_bf16.h>
#include <math.h>

#define B_  4
#define T_  4096
#define C_  1024
#define H_  64
#define BT  (B_*T_)

typedef unsigned int u32t;

// Pre-split bf16 hi/lo q,k,v (u32 = 2 packed bf16 cols; row = 32 u32 = 128B)
__device__ __align__(256) u32t g_qh[BT*32];
__device__ __align__(256) u32t g_ql[BT*32];
__device__ __align__(256) u32t g_kh[BT*32];
__device__ __align__(256) u32t g_kl[BT*32];
__device__ __align__(256) u32t g_vh[BT*32];
__device__ __align__(256) u32t g_vl[BT*32];

// ---- helpers ---------------------------------------------------------------
__device__ __forceinline__ u32t smem_u32(const void* p) {
    u32t a;
    asm("{ .reg .u64 t; cvta.to.shared.u64 t, %1; cvt.u32.u64 %0, t; }"
        : "=r"(a) : "l"(p));
    return a;
}

__device__ __forceinline__ void split_pair(float f0, float f1, u32t& hi, u32t& lo) {
    __nv_bfloat16 h0 = __float2bfloat16(f0);
    __nv_bfloat16 h1 = __float2bfloat16(f1);
    __nv_bfloat16 l0 = __float2bfloat16(f0 - __bfloat162float(h0));
    __nv_bfloat16 l1 = __float2bfloat16(f1 - __bfloat162float(h1));
    hi = (u32t)__bfloat16_as_ushort(h0) | ((u32t)__bfloat16_as_ushort(h1) << 16);
    lo = (u32t)__bfloat16_as_ushort(l0) | ((u32t)__bfloat16_as_ushort(l1) << 16);
}

__device__ __forceinline__ void ldsm_x4(u32t* r, u32t addr) {
    asm volatile("ldmatrix.sync.aligned.m8n8.x4.shared.b16 {%0,%1,%2,%3}, [%4];"
                 : "=r"(r[0]), "=r"(r[1]), "=r"(r[2]), "=r"(r[3]) : "r"(addr));
}
__device__ __forceinline__ void ldsm_x4_t(u32t* r, u32t addr) {
    asm volatile("ldmatrix.sync.aligned.m8n8.x4.trans.shared.b16 {%0,%1,%2,%3}, [%4];"
                 : "=r"(r[0]), "=r"(r[1]), "=r"(r[2]), "=r"(r[3]) : "r"(addr));
}
__device__ __forceinline__ void mma16816(float* d, const u32t* a, u32t b0, u32t b1) {
    asm volatile("mma.sync.aligned.m16n8k16.row.col.f32.bf16.bf16.f32 "
                 "{%0,%1,%2,%3}, {%4,%5,%6,%7}, {%8,%9}, {%0,%1,%2,%3};"
                 : "+f"(d[0]), "+f"(d[1]), "+f"(d[2]), "+f"(d[3])
                 : "r"(a[0]), "r"(a[1]), "r"(a[2]), "r"(a[3]), "r"(b0), "r"(b1));
}

__device__ __forceinline__ void cpa16(u32t dst, const void* src) {
    asm volatile("cp.async.ca.shared.global [%0], [%1], 16;"
                 :: "r"(dst), "l"(src) : "memory");
}
__device__ __forceinline__ void cpa_commit() {
    asm volatile("cp.async.commit_group;" ::: "memory");
}
__device__ __forceinline__ void cpa_wait0() {
    asm volatile("cp.async.wait_group 0;" ::: "memory");
}
__device__ __forceinline__ void cpa_wait1() {
    asm volatile("cp.async.wait_group 1;" ::: "memory");
}

// async-copy one 64-row bf16 tile (64 x 128B) global -> smem (144B row stride)
__device__ __forceinline__ void stage_tile_async(const u32t* __restrict__ gsrc,
                                                 u32t dst_base, int ltid) {
    #pragma unroll
    for (int i = 0; i < 4; i++) {
        int id = ltid + 128*i;          // 0..511
        int row = id >> 3, seg = id & 7;
        cpa16(dst_base + row*144 + seg*16, gsrc + row*32 + seg*4);
    }
}

// ---------------------------------------------------------------------------
// Kernel 1: QKV projection via bf16 split-precision HMMA, pipelined staging.
// grid = BT/128, block = 256. Epilogue writes bf16 hi/lo packed u32 arrays.
// ---------------------------------------------------------------------------
#define PXH 0
#define PXL 10240
#define PWH 20480
#define PWL 35840
#define PROJ_SMEM 51200

__global__ __launch_bounds__(256) void proj_tc_kernel(
        const float* __restrict__ x,
        const float* __restrict__ Wq,
        const float* __restrict__ Wk,
        const float* __restrict__ Wv)
{
    extern __shared__ char smem[];
    const u32t sb = smem_u32(smem);
    const int tid  = threadIdx.x;
    const int wid  = tid >> 5;
    const int lane = tid & 31;
    const int row0 = blockIdx.x * 128;
    const float* Ws[3] = {Wq, Wk, Wv};

    float acc[24][4] = {};

    const int a_row = (lane & 15);
    const int a_c8  = ((lane >> 4) & 1) * 8;
    const int b_row = (lane & 7) + ((lane >> 4) & 1) * 8;
    const int b_c8  = ((lane >> 3) & 1) * 8;

    float4 vx[4], vw[6];
    {
        #pragma unroll
        for (int i = 0; i < 4; i++) {
            int f4 = tid + 256*i; int r = f4 >> 3, c4 = (f4 & 7) * 4;
            vx[i] = *(const float4*)&x[(size_t)(row0 + r)*C_ + c4];
        }
        #pragma unroll
        for (int i = 0; i < 6; i++) {
            int f4 = tid + 256*i; int r = f4 >> 3, c4 = (f4 & 7) * 4;
            vw[i] = *(const float4*)(Ws[r >> 6] + (size_t)(r & 63)*C_ + c4);
        }
    }

    for (int ch = 0; ch < 32; ch++) {
        #pragma unroll
        for (int i = 0; i < 4; i++) {
            int f4 = tid + 256*i; int r = f4 >> 3, c4 = (f4 & 7) * 4;
            u32t h0, l0, h1, l1;
            split_pair(vx[i].x, vx[i].y, h0, l0);
            split_pair(vx[i].z, vx[i].w, h1, l1);
            char* ph = smem + PXH + r*80 + c4*2;
            char* pl = smem + PXL + r*80 + c4*2;
            *(u32t*)ph = h0; *(u32t*)(ph+4) = h1;
            *(u32t*)pl = l0; *(u32t*)(pl+4) = l1;
        }
        #pragma unroll
        for (int i = 0; i < 6; i++) {
            int f4 = tid + 256*i; int r = f4 >> 3, c4 = (f4 & 7) * 4;
            u32t h0, l0, h1, l1;
            split_pair(vw[i].x, vw[i].y, h0, l0);
            split_pair(vw[i].z, vw[i].w, h1, l1);
            char* ph = smem + PWH + r*80 + c4*2;
            char* pl = smem + PWL + r*80 + c4*2;
            *(u32t*)ph = h0; *(u32t*)(ph+4) = h1;
            *(u32t*)pl = l0; *(u32t*)(pl+4) = l1;
        }
        __syncthreads();

        if (ch < 31) {
            const int k0n = (ch + 1) * 32;
            #pragma unroll
            for (int i = 0; i < 4; i++) {
                int f4 = tid + 256*i; int r = f4 >> 3, c4 = (f4 & 7) * 4;
                vx[i] = *(const float4*)&x[(size_t)(row0 + r)*C_ + k0n + c4];
            }
            #pragma unroll
            for (int i = 0; i < 6; i++) {
                int f4 = tid + 256*i; int r = f4 >> 3, c4 = (f4 & 7) * 4;
                vw[i] = *(const float4*)(Ws[r >> 6] + (size_t)(r & 63)*C_ + k0n + c4);
            }
        }

        u32t xh[2][4], xl[2][4];
        #pragma unroll
        for (int s = 0; s < 2; s++) {
            u32t ab = (u32t)((16*wid + a_row)*80 + (a_c8 + 16*s)*2);
            ldsm_x4(xh[s], sb + PXH + ab);
            ldsm_x4(xl[s], sb + PXL + ab);
        }
        #pragma unroll
        for (int jp = 0; jp < 12; jp++) {
            #pragma unroll
            for (int s = 0; s < 2; s++) {
                u32t bb = (u32t)((16*jp + b_row)*80 + (b_c8 + 16*s)*2);
                u32t bh[4], bl[4];
                ldsm_x4(bh, sb + PWH + bb);
                ldsm_x4(bl, sb + PWL + bb);
                mma16816(acc[2*jp],   xh[s], bh[0], bh[1]);
                mma16816(acc[2*jp],   xh[s], bl[0], bl[1]);
                mma16816(acc[2*jp],   xl[s], bh[0], bh[1]);
                mma16816(acc[2*jp+1], xh[s], bh[2], bh[3]);
                mma16816(acc[2*jp+1], xh[s], bl[2], bl[3]);
                mma16816(acc[2*jp+1], xl[s], bh[2], bh[3]);
            }
        }
        __syncthreads();
    }

    // epilogue: split fp32 results into bf16 hi/lo packed u32 arrays
    const int q = lane & 3, r = lane >> 2;
    u32t* outsH[3] = {g_qh, g_kh, g_vh};
    u32t* outsL[3] = {g_ql, g_kl, g_vl};
    #pragma unroll
    for (int t = 0; t < 24; t++) {
        u32t* oh = outsH[t >> 3];
        u32t* ol = outsL[t >> 3];
        int uc = 4*(t & 7) + q;
        size_t rw = (size_t)(row0 + 16*wid + r);
        u32t h0, l0, h1, l1;
        split_pair(acc[t][0], acc[t][1], h0, l0);
        split_pair(acc[t][2], acc[t][3], h1, l1);
        oh[rw*32 + uc] = h0;  ol[rw*32 + uc] = l0;
        oh[(rw+8)*32 + uc] = h1;  ol[(rw+8)*32 + uc] = l1;
    }
}

// ---------------------------------------------------------------------------
// Kernel 2: flash-attention, bf16 split HMMA, causal, paired, split-KV,
// cp.async double-buffered K/V staging. grid = (32, B), block = 256.
// ---------------------------------------------------------------------------
#define AQH 0
#define AQL 9216
#define AKV 18432          // per-buffer: KH 0, KL 9216, VH 18432, VL 27648
#define KVB 36864          // bytes per KV buffer
#define GRP_BYTES (18432 + 2*KVB)          // 92160
#define MRG_MD (2*GRP_BYTES)               // 184320
#define MRG_OD (MRG_MD + 2048)
#define ATTN_SMEM (MRG_OD + 16384)         // 202752

__global__ __launch_bounds__(256) void attn_tc_kernel(float* __restrict__ out)
{
    extern __shared__ char smem[];
    const int tid  = threadIdx.x;
    const int g    = tid >> 7;
    const int ltid = tid & 127;
    const int wid  = ltid >> 5;
    const int lane = tid & 31;
    const int b    = blockIdx.y;
    const int pr   = blockIdx.x;
    const int q    = lane & 3;
    const int r    = lane >> 2;

    const u32t sbg = smem_u32(smem) + g * GRP_BYTES;

    const int a_row = (lane & 15);
    const int a_c8  = ((lane >> 4) & 1) * 8;
    const int b_row = (lane & 7) + ((lane >> 4) & 1) * 8;
    const int b_c8  = ((lane >> 3) & 1) * 8;
    const int v_row = (lane & 7) + ((lane >> 3) & 1) * 8;
    const int v_c8  = ((lane >> 4) & 1) * 8;

    const float scale = 0.125f;

    float* MD = (float*)(smem + MRG_MD);
    float* OD = (float*)(smem + MRG_OD);

    #pragma unroll 1
    for (int half = 0; half < 2; half++) {
        const int m0 = (half == 0 ? pr : 63 - pr) * 64;
        const int nt = m0/64 + 1;
        const int hsp = (nt + 1) >> 1;
        const int tb = g ? hsp : 0;
        const int te = g ? nt  : hsp;

        // prologue: stage Q and first KV tile
        {
            const size_t qr = (size_t)(b*T_ + m0) * 32;
            stage_tile_async(g_qh + qr, sbg + AQH, ltid);
            stage_tile_async(g_ql + qr, sbg + AQL, ltid);
            if (tb < te) {
                const size_t kr = (size_t)(b*T_ + tb*64) * 32;
                u32t kb = sbg + AKV;
                stage_tile_async(g_kh + kr, kb,         ltid);
                stage_tile_async(g_kl + kr, kb + 9216,  ltid);
                stage_tile_async(g_vh + kr, kb + 18432, ltid);
                stage_tile_async(g_vl + kr, kb + 27648, ltid);
            }
            cpa_commit();
            cpa_wait0();
            asm volatile("bar.sync %0, 128;" :: "r"(g+1) : "memory");
        }

        u32t qh[4][4], ql[4][4];
        #pragma unroll
        for (int s = 0; s < 4; s++) {
            u32t ab = (u32t)((16*wid + a_row)*144 + (a_c8 + 16*s)*2);
            ldsm_x4(qh[s], sbg + AQH + ab);
            ldsm_x4(ql[s], sbg + AQL + ab);
        }

        float o[8][4] = {};
        float m_i0 = -INFINITY, m_i1 = -INFINITY, l_i0 = 0.f, l_i1 = 0.f;
        const int row0g = m0 + 16*wid + r;
        const int row1g = row0g + 8;

        for (int t = tb; t < te; t++) {
            const int n0 = t * 64;
            const int cur = (t - tb) & 1;
            const u32t cb = sbg + AKV + cur * KVB;

            if (t + 1 < te) {           // prefetch next tile into other buffer
                const size_t kr = (size_t)(b*T_ + (t+1)*64) * 32;
                u32t nb = sbg + AKV + (cur ^ 1) * KVB;
                stage_tile_async(g_kh + kr, nb,         ltid);
                stage_tile_async(g_kl + kr, nb + 9216,  ltid);
                stage_tile_async(g_vh + kr, nb + 18432, ltid);
                stage_tile_async(g_vl + kr, nb + 27648, ltid);
                cpa_commit();
                cpa_wait1();
            } else {
                cpa_wait0();
            }
            asm volatile("bar.sync %0, 128;" :: "r"(g+1) : "memory");

            // ---- S = Q K^T ----
            float sf[8][4] = {};
            #pragma unroll
            for (int jp = 0; jp < 4; jp++) {
                #pragma unroll
                for (int s = 0; s < 4; s++) {
                    u32t bb = (u32t)((16*jp + b_row)*144 + (b_c8 + 16*s)*2);
                    u32t bh[4], bl[4];
                    ldsm_x4(bh, cb + bb);
                    ldsm_x4(bl, cb + 9216 + bb);
                    mma16816(sf[2*jp],   qh[s], bh[0], bh[1]);
                    mma16816(sf[2*jp],   qh[s], bl[0], bl[1]);
                    mma16816(sf[2*jp],   ql[s], bh[0], bh[1]);
                    mma16816(sf[2*jp+1], qh[s], bh[2], bh[3]);
                    mma16816(sf[2*jp+1], qh[s], bl[2], bl[3]);
                    mma16816(sf[2*jp+1], ql[s], bh[2], bh[3]);
                }
            }

            // ---- scale + causal mask ----
            if (n0 == m0) {
                #pragma unroll
                for (int j = 0; j < 8; j++) {
                    int c = n0 + 8*j + 2*q;
                    sf[j][0] = (c   > row0g) ? -INFINITY : sf[j][0]*scale;
                    sf[j][1] = (c+1 > row0g) ? -INFINITY : sf[j][1]*scale;
                    sf[j][2] = (c   > row1g) ? -INFINITY : sf[j][2]*scale;
                    sf[j][3] = (c+1 > row1g) ? -INFINITY : sf[j][3]*scale;
                }
            } else {
                #pragma unroll
                for (int j = 0; j < 8; j++)
                    #pragma unroll
                    for (int e = 0; e < 4; e++) sf[j][e] *= scale;
            }

            // ---- online softmax ----
            float mx0 = -INFINITY, mx1 = -INFINITY;
            #pragma unroll
            for (int j = 0; j < 8; j++) {
                mx0 = fmaxf(mx0, fmaxf(sf[j][0], sf[j][1]));
                mx1 = fmaxf(mx1, fmaxf(sf[j][2], sf[j][3]));
            }
            mx0 = fmaxf(mx0, __shfl_xor_sync(0xffffffffu, mx0, 1));
            mx0 = fmaxf(mx0, __shfl_xor_sync(0xffffffffu, mx0, 2));
            mx1 = fmaxf(mx1, __shfl_xor_sync(0xffffffffu, mx1, 1));
            mx1 = fmaxf(mx1, __shfl_xor_sync(0xffffffffu, mx1, 2));
            float mn0 = fmaxf(m_i0, mx0);
            float mn1 = fmaxf(m_i1, mx1);
            float al0 = __expf(m_i0 - mn0);
            float al1 = __expf(m_i1 - mn1);

            float rs0 = 0.f, rs1 = 0.f;
            u32t pah[4][4], pal[4][4];
            #pragma unroll
            for (int j = 0; j < 8; j++) {
                float p0 = __expf(sf[j][0] - mn0);
                float p1 = __expf(sf[j][1] - mn0);
                float p2 = __expf(sf[j][2] - mn1);
                float p3 = __expf(sf[j][3] - mn1);
                rs0 += p0 + p1; rs1 += p2 + p3;
                int t0 = j >> 1, hi2 = (j & 1) * 2;
                split_pair(p0, p1, pah[t0][hi2],   pal[t0][hi2]);
                split_pair(p2, p3, pah[t0][hi2+1], pal[t0][hi2+1]);
            }
            rs0 += __shfl_xor_sync(0xffffffffu, rs0, 1);
            rs0 += __shfl_xor_sync(0xffffffffu, rs0, 2);
            rs1 += __shfl_xor_sync(0xffffffffu, rs1, 1);
            rs1 += __shfl_xor_sync(0xffffffffu, rs1, 2);
            l_i0 = l_i0*al0 + rs0;  m_i0 = mn0;
            l_i1 = l_i1*al1 + rs1;  m_i1 = mn1;
            #pragma unroll
            for (int j = 0; j < 8; j++) {
                o[j][0] *= al0; o[j][1] *= al0;
                o[j][2] *= al1; o[j][3] *= al1;
            }

            // ---- O += P V ----
            #pragma unroll
            for (int jp = 0; jp < 4; jp++) {
                #pragma unroll
                for (int t0 = 0; t0 < 4; t0++) {
                    u32t vb = (u32t)((16*t0 + v_row)*144 + (16*jp + v_c8)*2);
                    u32t vh[4], vl[4];
                    ldsm_x4_t(vh, cb + 18432 + vb);
                    ldsm_x4_t(vl, cb + 27648 + vb);
                    mma16816(o[2*jp],   pah[t0], vh[0], vh[1]);
                    mma16816(o[2*jp],   pah[t0], vl[0], vl[1]);
                    mma16816(o[2*jp],   pal[t0], vh[0], vh[1]);
                    mma16816(o[2*jp+1], pah[t0], vh[2], vh[3]);
                    mma16816(o[2*jp+1], pah[t0], vl[2], vl[3]);
                    mma16816(o[2*jp+1], pal[t0], vh[2], vh[3]);
                }
            }
            asm volatile("bar.sync %0, 128;" :: "r"(g+1) : "memory");
        }

        // ---- merge partials across the two groups ----
        if (g == 1) {
            MD[ltid*4+0] = m_i0; MD[ltid*4+1] = m_i1;
            MD[ltid*4+2] = l_i0; MD[ltid*4+3] = l_i1;
            #pragma unroll
            for (int j = 0; j < 8; j++)
                #pragma unroll
                for (int e = 0; e < 4; e++)
                    OD[ltid*32 + j*4 + e] = o[j][e];
        }
        __syncthreads();
        if (g == 0) {
            float m1_0 = MD[ltid*4+0], m1_1 = MD[ltid*4+1];
            float l1_0 = MD[ltid*4+2], l1_1 = MD[ltid*4+3];
            float mn0 = fmaxf(m_i0, m1_0);
            float mn1 = fmaxf(m_i1, m1_1);
            float a0 = __expf(m_i0 - mn0), b0 = __expf(m1_0 - mn0);
            float a1 = __expf(m_i1 - mn1), b1 = __expf(m1_1 - mn1);
            float lt0 = l_i0*a0 + l1_0*b0;
            float lt1 = l_i1*a1 + l1_1*b1;
            float inv0 = 1.0f / lt0;
            float inv1 = 1.0f / lt1;
            float* ob = out + (size_t)(b*T_) * H_;
            #pragma unroll
            for (int j = 0; j < 8; j++) {
                int col = 8*j + 2*q;
                float o0 = (o[j][0]*a0 + OD[ltid*32 + j*4 + 0]*b0) * inv0;
                float o1 = (o[j][1]*a0 + OD[ltid*32 + j*4 + 1]*b0) * inv0;
                float o2 = (o[j][2]*a1 + OD[ltid*32 + j*4 + 2]*b1) * inv1;
                float o3 = (o[j][3]*a1 + OD[ltid*32 + j*4 + 3]*b1) * inv1;
                *(float2*)&ob[(size_t)row0g*H_ + col] = make_float2(o0, o1);
                *(float2*)&ob[(size_t)row1g*H_ + col] = make_float2(o2, o3);
            }
        }
        __syncthreads();
    }
}

// ---------------------------------------------------------------------------
extern "C" void kernel_launch(void* const* d_in, const int* in_sizes, int n_in,
                              void* d_out, int out_size)
{
    const float* x  = (const float*)d_in[0];
    const float* Wq = (const float*)d_in[1];
    const float* Wk = (const float*)d_in[2];
    const float* Wv = (const float*)d_in[3];
    float* out = (float*)d_out;

    cudaFuncSetAttribute(proj_tc_kernel,
                         cudaFuncAttributeMaxDynamicSharedMemorySize, PROJ_SMEM);
    cudaFuncSetAttribute(attn_tc_kernel,
                         cudaFuncAttributeMaxDynamicSharedMemorySize, ATTN_SMEM);

    proj_tc_kernel<<<BT/128, 256, PROJ_SMEM>>>(x, Wq, Wk, Wv);
    attn_tc_kernel<<<dim3(32, B_), 256, ATTN_SMEM>>>(out);
}

// round 11
// speedup vs baseline: 9.2027x; 1.3311x over previous
#include <cuda_runtime.h>
#include <cuda_bf16.h>
#include <cuda_fp16.h>
#include <math.h>

#define B_  4
#define T_  4096
#define C_  1024
#define H_  64
#define BT  (B_*T_)

typedef unsigned int u32t;

// Pre-split bf16 hi/lo q,k (u32 = 2 packed bf16 cols; row = 32 u32 = 128B)
__device__ __align__(256) u32t g_qh[BT*32];
__device__ __align__(256) u32t g_ql[BT*32];
__device__ __align__(256) u32t g_kh[BT*32];
__device__ __align__(256) u32t g_kl[BT*32];
// V as packed fp16 (single precision term for PV)
__device__ __align__(256) u32t g_vf[BT*32];
// Pre-split W (3 x 64 x 1024 -> bf16 hi/lo, u32 = 2 cols; row = 512 u32)
__device__ __align__(256) u32t g_wh[192*512];
__device__ __align__(256) u32t g_wl[192*512];

// ---- helpers ---------------------------------------------------------------
__device__ __forceinline__ u32t smem_u32(const void* p) {
    u32t a;
    asm("{ .reg .u64 t; cvta.to.shared.u64 t, %1; cvt.u32.u64 %0, t; }"
        : "=r"(a) : "l"(p));
    return a;
}

__device__ __forceinline__ void split_pair(float f0, float f1, u32t& hi, u32t& lo) {
    __nv_bfloat16 h0 = __float2bfloat16(f0);
    __nv_bfloat16 h1 = __float2bfloat16(f1);
    __nv_bfloat16 l0 = __float2bfloat16(f0 - __bfloat162float(h0));
    __nv_bfloat16 l1 = __float2bfloat16(f1 - __bfloat162float(h1));
    hi = (u32t)__bfloat16_as_ushort(h0) | ((u32t)__bfloat16_as_ushort(h1) << 16);
    lo = (u32t)__bfloat16_as_ushort(l0) | ((u32t)__bfloat16_as_ushort(l1) << 16);
}

__device__ __forceinline__ u32t h2pack(float f0, float f1) {
    __half2 h = __floats2half2_rn(f0, f1);   // x = f0 (low half)
    return *(u32t*)&h;
}

__device__ __forceinline__ void ldsm_x4(u32t* r, u32t addr) {
    asm volatile("ldmatrix.sync.aligned.m8n8.x4.shared.b16 {%0,%1,%2,%3}, [%4];"
                 : "=r"(r[0]), "=r"(r[1]), "=r"(r[2]), "=r"(r[3]) : "r"(addr));
}
__device__ __forceinline__ void ldsm_x4_t(u32t* r, u32t addr) {
    asm volatile("ldmatrix.sync.aligned.m8n8.x4.trans.shared.b16 {%0,%1,%2,%3}, [%4];"
                 : "=r"(r[0]), "=r"(r[1]), "=r"(r[2]), "=r"(r[3]) : "r"(addr));
}
__device__ __forceinline__ void mma16816(float* d, const u32t* a, u32t b0, u32t b1) {
    asm volatile("mma.sync.aligned.m16n8k16.row.col.f32.bf16.bf16.f32 "
                 "{%0,%1,%2,%3}, {%4,%5,%6,%7}, {%8,%9}, {%0,%1,%2,%3};"
                 : "+f"(d[0]), "+f"(d[1]), "+f"(d[2]), "+f"(d[3])
                 : "r"(a[0]), "r"(a[1]), "r"(a[2]), "r"(a[3]), "r"(b0), "r"(b1));
}
__device__ __forceinline__ void mma16816h(float* d, const u32t* a, u32t b0, u32t b1) {
    asm volatile("mma.sync.aligned.m16n8k16.row.col.f32.f16.f16.f32 "
                 "{%0,%1,%2,%3}, {%4,%5,%6,%7}, {%8,%9}, {%0,%1,%2,%3};"
                 : "+f"(d[0]), "+f"(d[1]), "+f"(d[2]), "+f"(d[3])
                 : "r"(a[0]), "r"(a[1]), "r"(a[2]), "r"(a[3]), "r"(b0), "r"(b1));
}

__device__ __forceinline__ void cpa16(u32t dst, const void* src) {
    asm volatile("cp.async.ca.shared.global [%0], [%1], 16;"
                 :: "r"(dst), "l"(src) : "memory");
}
__device__ __forceinline__ void cpa_commit() {
    asm volatile("cp.async.commit_group;" ::: "memory");
}
__device__ __forceinline__ void cpa_wait0() {
    asm volatile("cp.async.wait_group 0;" ::: "memory");
}
__device__ __forceinline__ void cpa_wait1() {
    asm volatile("cp.async.wait_group 1;" ::: "memory");
}

// async-copy one 64-row tile (64 x 128B) global -> smem (144B row stride)
__device__ __forceinline__ void stage_tile_async(const u32t* __restrict__ gsrc,
                                                 u32t dst_base, int ltid) {
    #pragma unroll
    for (int i = 0; i < 4; i++) {
        int id = ltid + 128*i;
        int row = id >> 3, seg = id & 7;
        cpa16(dst_base + row*144 + seg*16, gsrc + row*32 + seg*4);
    }
}

// ---------------------------------------------------------------------------
// Kernel 0: one-shot W split (3x64x1024 fp32 -> bf16 hi/lo packed u32)
// ---------------------------------------------------------------------------
__global__ __launch_bounds__(256) void wsplit_kernel(
        const float* __restrict__ Wq,
        const float* __restrict__ Wk,
        const float* __restrict__ Wv)
{
    const int id = blockIdx.x * 256 + threadIdx.x;   // 0..98303
    const int row = id >> 9;        // 0..191
    const int c   = id & 511;       // u32 col
    const float* W = (row < 64) ? Wq : (row < 128) ? Wk : Wv;
    const float* p = W + (size_t)(row & 63) * C_ + 2*c;
    u32t hi, lo;
    split_pair(p[0], p[1], hi, lo);
    g_wh[id] = hi;
    g_wl[id] = lo;
}

// ---------------------------------------------------------------------------
// Kernel 1: QKV projection via bf16 split-precision HMMA.
// grid = BT/128, block = 256. x staged via reg-prefetch + split;
// W staged via cp.async from pre-split g_wh/g_wl (double-buffered).
// Epilogue: q,k -> bf16 hi/lo arrays; v -> fp16 array.
// ---------------------------------------------------------------------------
#define PXH 0
#define PXL 10240
#define PWB 20480           // W buffers: 2 x 30720 (hi at +0, lo at +15360)
#define PROJ_SMEM (20480 + 2*30720)   // 81920

__global__ __launch_bounds__(256) void proj_tc_kernel(const float* __restrict__ x)
{
    extern __shared__ char smem[];
    const u32t sb = smem_u32(smem);
    const int tid  = threadIdx.x;
    const int wid  = tid >> 5;
    const int lane = tid & 31;
    const int row0 = blockIdx.x * 128;

    float acc[24][4] = {};

    const int a_row = (lane & 15);
    const int a_c8  = ((lane >> 4) & 1) * 8;
    const int b_row = (lane & 7) + ((lane >> 4) & 1) * 8;
    const int b_c8  = ((lane >> 3) & 1) * 8;

    // prologue: W chunk 0 via cp.async, x chunk 0 via registers
    #pragma unroll
    for (int i = 0; i < 3; i++) {
        int id = tid + 256*i;                    // 0..767
        int r = id >> 2, seg = id & 3;
        cpa16(sb + PWB + r*80 + seg*16,          g_wh + r*512 + seg*4);
        cpa16(sb + PWB + 15360 + r*80 + seg*16,  g_wl + r*512 + seg*4);
    }
    cpa_commit();

    float4 vx[4];
    #pragma unroll
    for (int i = 0; i < 4; i++) {
        int f4 = tid + 256*i; int r = f4 >> 3, c4 = (f4 & 7) * 4;
        vx[i] = *(const float4*)&x[(size_t)(row0 + r)*C_ + c4];
    }

    for (int ch = 0; ch < 32; ch++) {
        const u32t wb = sb + PWB + (ch & 1) * 30720;
        // store prefetched x to smem (split hi/lo)
        #pragma unroll
        for (int i = 0; i < 4; i++) {
            int f4 = tid + 256*i; int r = f4 >> 3, c4 = (f4 & 7) * 4;
            u32t h0, l0, h1, l1;
            split_pair(vx[i].x, vx[i].y, h0, l0);
            split_pair(vx[i].z, vx[i].w, h1, l1);
            char* ph = smem + PXH + r*80 + c4*2;
            char* pl = smem + PXL + r*80 + c4*2;
            *(u32t*)ph = h0; *(u32t*)(ph+4) = h1;
            *(u32t*)pl = l0; *(u32t*)(pl+4) = l1;
        }
        cpa_wait0();
        __syncthreads();

        if (ch < 31) {
            const int k0n = (ch + 1) * 32;
            const int c16 = (ch + 1) * 16;
            #pragma unroll
            for (int i = 0; i < 4; i++) {
                int f4 = tid + 256*i; int r = f4 >> 3, c4 = (f4 & 7) * 4;
                vx[i] = *(const float4*)&x[(size_t)(row0 + r)*C_ + k0n + c4];
            }
            const u32t nb = sb + PWB + ((ch + 1) & 1) * 30720;
            #pragma unroll
            for (int i = 0; i < 3; i++) {
                int id = tid + 256*i;
                int r = id >> 2, seg = id & 3;
                cpa16(nb + r*80 + seg*16,         g_wh + r*512 + c16 + seg*4);
                cpa16(nb + 15360 + r*80 + seg*16, g_wl + r*512 + c16 + seg*4);
            }
            cpa_commit();
        }

        u32t xh[2][4], xl[2][4];
        #pragma unroll
        for (int s = 0; s < 2; s++) {
            u32t ab = (u32t)((16*wid + a_row)*80 + (a_c8 + 16*s)*2);
            ldsm_x4(xh[s], sb + PXH + ab);
            ldsm_x4(xl[s], sb + PXL + ab);
        }
        #pragma unroll
        for (int jp = 0; jp < 12; jp++) {
            #pragma unroll
            for (int s = 0; s < 2; s++) {
                u32t bb = (u32t)((16*jp + b_row)*80 + (b_c8 + 16*s)*2);
                u32t bh[4], bl[4];
                ldsm_x4(bh, wb + bb);
                ldsm_x4(bl, wb + 15360 + bb);
                mma16816(acc[2*jp],   xh[s], bh[0], bh[1]);
                mma16816(acc[2*jp],   xh[s], bl[0], bl[1]);
                mma16816(acc[2*jp],   xl[s], bh[0], bh[1]);
                mma16816(acc[2*jp+1], xh[s], bh[2], bh[3]);
                mma16816(acc[2*jp+1], xh[s], bl[2], bl[3]);
                mma16816(acc[2*jp+1], xl[s], bh[2], bh[3]);
            }
        }
        __syncthreads();
    }

    // epilogue
    const int q = lane & 3, r = lane >> 2;
    #pragma unroll
    for (int t = 0; t < 24; t++) {
        int uc = 4*(t & 7) + q;
        size_t rw = (size_t)(row0 + 16*wid + r);
        if (t < 16) {                       // q, k: bf16 hi/lo
            u32t* oh = (t < 8) ? g_qh : g_kh;
            u32t* ol = (t < 8) ? g_ql : g_kl;
            u32t h0, l0, h1, l1;
            split_pair(acc[t][0], acc[t][1], h0, l0);
            split_pair(acc[t][2], acc[t][3], h1, l1);
            oh[rw*32 + uc] = h0;      ol[rw*32 + uc] = l0;
            oh[(rw+8)*32 + uc] = h1;  ol[(rw+8)*32 + uc] = l1;
        } else {                            // v: fp16
            g_vf[rw*32 + uc]     = h2pack(acc[t][0], acc[t][1]);
            g_vf[(rw+8)*32 + uc] = h2pack(acc[t][2], acc[t][3]);
        }
    }
}

// ---------------------------------------------------------------------------
// Kernel 2: flash-attention. S = QK^T in bf16 3-term split (accurate logits),
// PV in single-term fp16. Causal, paired, split-KV across 2 warpgroups,
// cp.async double-buffered staging. grid = (32, B), block = 256.
// ---------------------------------------------------------------------------
#define AQH 0
#define AQL 9216
#define AKV 18432          // per-buffer: KH 0, KL 9216, VF 18432
#define KVB 27648
#define GRP_BYTES (18432 + 2*KVB)          // 73728
#define MRG_MD (2*GRP_BYTES)               // 147456
#define MRG_OD (MRG_MD + 2048)
#define ATTN_SMEM (MRG_OD + 16384)         // 165888

__global__ __launch_bounds__(256) void attn_tc_kernel(float* __restrict__ out)
{
    extern __shared__ char smem[];
    const int tid  = threadIdx.x;
    const int g    = tid >> 7;
    const int ltid = tid & 127;
    const int wid  = ltid >> 5;
    const int lane = tid & 31;
    const int b    = blockIdx.y;
    const int pr   = blockIdx.x;
    const int q    = lane & 3;
    const int r    = lane >> 2;

    const u32t sbg = smem_u32(smem) + g * GRP_BYTES;

    const int a_row = (lane & 15);
    const int a_c8  = ((lane >> 4) & 1) * 8;
    const int b_row = (lane & 7) + ((lane >> 4) & 1) * 8;
    const int b_c8  = ((lane >> 3) & 1) * 8;
    const int v_row = (lane & 7) + ((lane >> 3) & 1) * 8;
    const int v_c8  = ((lane >> 4) & 1) * 8;

    const float scale = 0.125f;

    float* MD = (float*)(smem + MRG_MD);
    float* OD = (float*)(smem + MRG_OD);

    #pragma unroll 1
    for (int half = 0; half < 2; half++) {
        const int m0 = (half == 0 ? pr : 63 - pr) * 64;
        const int nt = m0/64 + 1;
        const int hsp = (nt + 1) >> 1;
        const int tb = g ? hsp : 0;
        const int te = g ? nt  : hsp;

        // prologue: stage Q and first KV tile
        {
            const size_t qr = (size_t)(b*T_ + m0) * 32;
            stage_tile_async(g_qh + qr, sbg + AQH, ltid);
            stage_tile_async(g_ql + qr, sbg + AQL, ltid);
            if (tb < te) {
                const size_t kr = (size_t)(b*T_ + tb*64) * 32;
                u32t kb = sbg + AKV;
                stage_tile_async(g_kh + kr, kb,         ltid);
                stage_tile_async(g_kl + kr, kb + 9216,  ltid);
                stage_tile_async(g_vf + kr, kb + 18432, ltid);
            }
            cpa_commit();
            cpa_wait0();
            asm volatile("bar.sync %0, 128;" :: "r"(g+1) : "memory");
        }

        u32t qh[4][4], ql[4][4];
        #pragma unroll
        for (int s = 0; s < 4; s++) {
            u32t ab = (u32t)((16*wid + a_row)*144 + (a_c8 + 16*s)*2);
            ldsm_x4(qh[s], sbg + AQH + ab);
            ldsm_x4(ql[s], sbg + AQL + ab);
        }

        float o[8][4] = {};
        float m_i0 = -INFINITY, m_i1 = -INFINITY, l_i0 = 0.f, l_i1 = 0.f;
        const int row0g = m0 + 16*wid + r;
        const int row1g = row0g + 8;

        for (int t = tb; t < te; t++) {
            const int n0 = t * 64;
            const int cur = (t - tb) & 1;
            const u32t cb = sbg + AKV + cur * KVB;

            if (t + 1 < te) {
                const size_t kr = (size_t)(b*T_ + (t+1)*64) * 32;
                u32t nb = sbg + AKV + (cur ^ 1) * KVB;
                stage_tile_async(g_kh + kr, nb,         ltid);
                stage_tile_async(g_kl + kr, nb + 9216,  ltid);
                stage_tile_async(g_vf + kr, nb + 18432, ltid);
                cpa_commit();
                cpa_wait1();
            } else {
                cpa_wait0();
            }
            asm volatile("bar.sync %0, 128;" :: "r"(g+1) : "memory");

            // ---- S = Q K^T (bf16 3-term) ----
            float sf[8][4] = {};
            #pragma unroll
            for (int jp = 0; jp < 4; jp++) {
                #pragma unroll
                for (int s = 0; s < 4; s++) {
                    u32t bb = (u32t)((16*jp + b_row)*144 + (b_c8 + 16*s)*2);
                    u32t bh[4], bl[4];
                    ldsm_x4(bh, cb + bb);
                    ldsm_x4(bl, cb + 9216 + bb);
                    mma16816(sf[2*jp],   qh[s], bh[0], bh[1]);
                    mma16816(sf[2*jp],   qh[s], bl[0], bl[1]);
                    mma16816(sf[2*jp],   ql[s], bh[0], bh[1]);
                    mma16816(sf[2*jp+1], qh[s], bh[2], bh[3]);
                    mma16816(sf[2*jp+1], qh[s], bl[2], bl[3]);
                    mma16816(sf[2*jp+1], ql[s], bh[2], bh[3]);
                }
            }

            // ---- scale + causal mask ----
            if (n0 == m0) {
                #pragma unroll
                for (int j = 0; j < 8; j++) {
                    int c = n0 + 8*j + 2*q;
                    sf[j][0] = (c   > row0g) ? -INFINITY : sf[j][0]*scale;
                    sf[j][1] = (c+1 > row0g) ? -INFINITY : sf[j][1]*scale;
                    sf[j][2] = (c   > row1g) ? -INFINITY : sf[j][2]*scale;
                    sf[j][3] = (c+1 > row1g) ? -INFINITY : sf[j][3]*scale;
                }
            } else {
                #pragma unroll
                for (int j = 0; j < 8; j++)
                    #pragma unroll
                    for (int e = 0; e < 4; e++) sf[j][e] *= scale;
            }

            // ---- online softmax ----
            float mx0 = -INFINITY, mx1 = -INFINITY;
            #pragma unroll
            for (int j = 0; j < 8; j++) {
                mx0 = fmaxf(mx0, fmaxf(sf[j][0], sf[j][1]));
                mx1 = fmaxf(mx1, fmaxf(sf[j][2], sf[j][3]));
            }
            mx0 = fmaxf(mx0, __shfl_xor_sync(0xffffffffu, mx0, 1));
            mx0 = fmaxf(mx0, __shfl_xor_sync(0xffffffffu, mx0, 2));
            mx1 = fmaxf(mx1, __shfl_xor_sync(0xffffffffu, mx1, 1));
            mx1 = fmaxf(mx1, __shfl_xor_sync(0xffffffffu, mx1, 2));
            float mn0 = fmaxf(m_i0, mx0);
            float mn1 = fmaxf(m_i1, mx1);
            float al0 = __expf(m_i0 - mn0);
            float al1 = __expf(m_i1 - mn1);

            float rs0 = 0.f, rs1 = 0.f;
            u32t pa[4][4];                       // fp16 A-frags for PV
            #pragma unroll
            for (int j = 0; j < 8; j++) {
                float p0 = __expf(sf[j][0] - mn0);
                float p1 = __expf(sf[j][1] - mn0);
                float p2 = __expf(sf[j][2] - mn1);
                float p3 = __expf(sf[j][3] - mn1);
                rs0 += p0 + p1; rs1 += p2 + p3;
                int t0 = j >> 1, hi2 = (j & 1) * 2;
                pa[t0][hi2]   = h2pack(p0, p1);
                pa[t0][hi2+1] = h2pack(p2, p3);
            }
            rs0 += __shfl_xor_sync(0xffffffffu, rs0, 1);
            rs0 += __shfl_xor_sync(0xffffffffu, rs0, 2);
            rs1 += __shfl_xor_sync(0xffffffffu, rs1, 1);
            rs1 += __shfl_xor_sync(0xffffffffu, rs1, 2);
            l_i0 = l_i0*al0 + rs0;  m_i0 = mn0;
            l_i1 = l_i1*al1 + rs1;  m_i1 = mn1;
            #pragma unroll
            for (int j = 0; j < 8; j++) {
                o[j][0] *= al0; o[j][1] *= al0;
                o[j][2] *= al1; o[j][3] *= al1;
            }

            // ---- O += P V (fp16 single-term) ----
            #pragma unroll
            for (int jp = 0; jp < 4; jp++) {
                #pragma unroll
                for (int t0 = 0; t0 < 4; t0++) {
                    u32t vb = (u32t)((16*t0 + v_row)*144 + (16*jp + v_c8)*2);
                    u32t vh[4];
                    ldsm_x4_t(vh, cb + 18432 + vb);
                    mma16816h(o[2*jp],   pa[t0], vh[0], vh[1]);
                    mma16816h(o[2*jp+1], pa[t0], vh[2], vh[3]);
                }
            }
            asm volatile("bar.sync %0, 128;" :: "r"(g+1) : "memory");
        }

        // ---- merge partials across the two groups ----
        if (g == 1) {
            MD[ltid*4+0] = m_i0; MD[ltid*4+1] = m_i1;
            MD[ltid*4+2] = l_i0; MD[ltid*4+3] = l_i1;
            #pragma unroll
            for (int j = 0; j < 8; j++)
                #pragma unroll
                for (int e = 0; e < 4; e++)
                    OD[ltid*32 + j*4 + e] = o[j][e];
        }
        __syncthreads();
        if (g == 0) {
            float m1_0 = MD[ltid*4+0], m1_1 = MD[ltid*4+1];
            float l1_0 = MD[ltid*4+2], l1_1 = MD[ltid*4+3];
            float mn0 = fmaxf(m_i0, m1_0);
            float mn1 = fmaxf(m_i1, m1_1);
            float a0 = __expf(m_i0 - mn0), b0 = __expf(m1_0 - mn0);
            float a1 = __expf(m_i1 - mn1), b1 = __expf(m1_1 - mn1);
            float lt0 = l_i0*a0 + l1_0*b0;
            float lt1 = l_i1*a1 + l1_1*b1;
            float inv0 = 1.0f / lt0;
            float inv1 = 1.0f / lt1;
            float* ob = out + (size_t)(b*T_) * H_;
            #pragma unroll
            for (int j = 0; j < 8; j++) {
                int col = 8*j + 2*q;
                float o0 = (o[j][0]*a0 + OD[ltid*32 + j*4 + 0]*b0) * inv0;
                float o1 = (o[j][1]*a0 + OD[ltid*32 + j*4 + 1]*b0) * inv0;
                float o2 = (o[j][2]*a1 + OD[ltid*32 + j*4 + 2]*b1) * inv1;
                float o3 = (o[j][3]*a1 + OD[ltid*32 + j*4 + 3]*b1) * inv1;
                *(float2*)&ob[(size_t)row0g*H_ + col] = make_float2(o0, o1);
                *(float2*)&ob[(size_t)row1g*H_ + col] = make_float2(o2, o3);
            }
        }
        __syncthreads();
    }
}

// ---------------------------------------------------------------------------
extern "C" void kernel_launch(void* const* d_in, const int* in_sizes, int n_in,
                              void* d_out, int out_size)
{
    const float* x  = (const float*)d_in[0];
    const float* Wq = (const float*)d_in[1];
    const float* Wk = (const float*)d_in[2];
    const float* Wv = (const float*)d_in[3];
    float* out = (float*)d_out;

    cudaFuncSetAttribute(proj_tc_kernel,
                         cudaFuncAttributeMaxDynamicSharedMemorySize, PROJ_SMEM);
    cudaFuncSetAttribute(attn_tc_kernel,
                         cudaFuncAttributeMaxDynamicSharedMemorySize, ATTN_SMEM);

    wsplit_kernel<<<384, 256>>>(Wq, Wk, Wv);
    proj_tc_kernel<<<BT/128, 256, PROJ_SMEM>>>(x);
    attn_tc_kernel<<<dim3(32, B_), 256, ATTN_SMEM>>>(out);
}

// round 12
// speedup vs baseline: 9.2194x; 1.0018x over previous
#include <cuda_runtime.h>
#include <cuda_bf16.h>
#include <cuda_fp16.h>
#include <math.h>

#define B_  4
#define T_  4096
#define C_  1024
#define H_  64
#define BT  (B_*T_)

typedef unsigned int u32t;

// Pre-split bf16 hi/lo q,k (u32 = 2 packed bf16 cols; row = 32 u32 = 128B)
// q is PRE-SCALED by 0.125 (attention scale) at projection epilogue.
__device__ __align__(256) u32t g_qh[BT*32];
__device__ __align__(256) u32t g_ql[BT*32];
__device__ __align__(256) u32t g_kh[BT*32];
__device__ __align__(256) u32t g_kl[BT*32];
// V as packed fp16 (single precision term for PV)
__device__ __align__(256) u32t g_vf[BT*32];
// Pre-split W (3 x 64 x 1024 -> bf16 hi/lo, u32 = 2 cols; row = 512 u32)
__device__ __align__(256) u32t g_wh[192*512];
__device__ __align__(256) u32t g_wl[192*512];

// ---- helpers ---------------------------------------------------------------
__device__ __forceinline__ u32t smem_u32(const void* p) {
    u32t a;
    asm("{ .reg .u64 t; cvta.to.shared.u64 t, %1; cvt.u32.u64 %0, t; }"
        : "=r"(a) : "l"(p));
    return a;
}

__device__ __forceinline__ void split_pair(float f0, float f1, u32t& hi, u32t& lo) {
    __nv_bfloat16 h0 = __float2bfloat16(f0);
    __nv_bfloat16 h1 = __float2bfloat16(f1);
    __nv_bfloat16 l0 = __float2bfloat16(f0 - __bfloat162float(h0));
    __nv_bfloat16 l1 = __float2bfloat16(f1 - __bfloat162float(h1));
    hi = (u32t)__bfloat16_as_ushort(h0) | ((u32t)__bfloat16_as_ushort(h1) << 16);
    lo = (u32t)__bfloat16_as_ushort(l0) | ((u32t)__bfloat16_as_ushort(l1) << 16);
}

__device__ __forceinline__ u32t h2pack(float f0, float f1) {
    __half2 h = __floats2half2_rn(f0, f1);
    return *(u32t*)&h;
}

__device__ __forceinline__ void ldsm_x4(u32t* r, u32t addr) {
    asm volatile("ldmatrix.sync.aligned.m8n8.x4.shared.b16 {%0,%1,%2,%3}, [%4];"
                 : "=r"(r[0]), "=r"(r[1]), "=r"(r[2]), "=r"(r[3]) : "r"(addr));
}
__device__ __forceinline__ void ldsm_x4_t(u32t* r, u32t addr) {
    asm volatile("ldmatrix.sync.aligned.m8n8.x4.trans.shared.b16 {%0,%1,%2,%3}, [%4];"
                 : "=r"(r[0]), "=r"(r[1]), "=r"(r[2]), "=r"(r[3]) : "r"(addr));
}
__device__ __forceinline__ void mma16816(float* d, const u32t* a, u32t b0, u32t b1) {
    asm volatile("mma.sync.aligned.m16n8k16.row.col.f32.bf16.bf16.f32 "
                 "{%0,%1,%2,%3}, {%4,%5,%6,%7}, {%8,%9}, {%0,%1,%2,%3};"
                 : "+f"(d[0]), "+f"(d[1]), "+f"(d[2]), "+f"(d[3])
                 : "r"(a[0]), "r"(a[1]), "r"(a[2]), "r"(a[3]), "r"(b0), "r"(b1));
}
__device__ __forceinline__ void mma16816h(float* d, const u32t* a, u32t b0, u32t b1) {
    asm volatile("mma.sync.aligned.m16n8k16.row.col.f32.f16.f16.f32 "
                 "{%0,%1,%2,%3}, {%4,%5,%6,%7}, {%8,%9}, {%0,%1,%2,%3};"
                 : "+f"(d[0]), "+f"(d[1]), "+f"(d[2]), "+f"(d[3])
                 : "r"(a[0]), "r"(a[1]), "r"(a[2]), "r"(a[3]), "r"(b0), "r"(b1));
}

__device__ __forceinline__ void cpa16(u32t dst, const void* src) {
    asm volatile("cp.async.ca.shared.global [%0], [%1], 16;"
                 :: "r"(dst), "l"(src) : "memory");
}
__device__ __forceinline__ void cpa_commit() {
    asm volatile("cp.async.commit_group;" ::: "memory");
}
__device__ __forceinline__ void cpa_wait0() {
    asm volatile("cp.async.wait_group 0;" ::: "memory");
}
__device__ __forceinline__ void cpa_wait1() {
    asm volatile("cp.async.wait_group 1;" ::: "memory");
}

// async-copy one 64-row tile (64 x 128B) global -> smem (144B row stride)
__device__ __forceinline__ void stage_tile_async(const u32t* __restrict__ gsrc,
                                                 u32t dst_base, int ltid) {
    #pragma unroll
    for (int i = 0; i < 4; i++) {
        int id = ltid + 128*i;
        int row = id >> 3, seg = id & 7;
        cpa16(dst_base + row*144 + seg*16, gsrc + row*32 + seg*4);
    }
}

// ---------------------------------------------------------------------------
// Kernel 0: one-shot W split (3x64x1024 fp32 -> bf16 hi/lo packed u32)
// ---------------------------------------------------------------------------
__global__ __launch_bounds__(256) void wsplit_kernel(
        const float* __restrict__ Wq,
        const float* __restrict__ Wk,
        const float* __restrict__ Wv)
{
    const int id = blockIdx.x * 256 + threadIdx.x;
    const int row = id >> 9;
    const int c   = id & 511;
    const float* W = (row < 64) ? Wq : (row < 128) ? Wk : Wv;
    const float* p = W + (size_t)(row & 63) * C_ + 2*c;
    u32t hi, lo;
    split_pair(p[0], p[1], hi, lo);
    g_wh[id] = hi;
    g_wl[id] = lo;
}

// ---------------------------------------------------------------------------
// Kernel 1: QKV projection via bf16 split-precision HMMA.
// grid = BT/128, block = 256. x staged via reg-prefetch + split;
// W staged via cp.async from pre-split g_wh/g_wl (double-buffered).
// Epilogue: q (x0.125), k -> bf16 hi/lo arrays; v -> fp16 array.
// MMA loop is accumulator-major (s outer, jp inner) for pipelining.
// ---------------------------------------------------------------------------
#define PXH 0
#define PXL 10240
#define PWB 20480
#define PROJ_SMEM (20480 + 2*30720)   // 81920

__global__ __launch_bounds__(256) void proj_tc_kernel(const float* __restrict__ x)
{
    extern __shared__ char smem[];
    const u32t sb = smem_u32(smem);
    const int tid  = threadIdx.x;
    const int wid  = tid >> 5;
    const int lane = tid & 31;
    const int row0 = blockIdx.x * 128;

    float acc[24][4] = {};

    const int a_row = (lane & 15);
    const int a_c8  = ((lane >> 4) & 1) * 8;
    const int b_row = (lane & 7) + ((lane >> 4) & 1) * 8;
    const int b_c8  = ((lane >> 3) & 1) * 8;

    #pragma unroll
    for (int i = 0; i < 3; i++) {
        int id = tid + 256*i;
        int r = id >> 2, seg = id & 3;
        cpa16(sb + PWB + r*80 + seg*16,          g_wh + r*512 + seg*4);
        cpa16(sb + PWB + 15360 + r*80 + seg*16,  g_wl + r*512 + seg*4);
    }
    cpa_commit();

    float4 vx[4];
    #pragma unroll
    for (int i = 0; i < 4; i++) {
        int f4 = tid + 256*i; int r = f4 >> 3, c4 = (f4 & 7) * 4;
        vx[i] = *(const float4*)&x[(size_t)(row0 + r)*C_ + c4];
    }

    for (int ch = 0; ch < 32; ch++) {
        const u32t wb = sb + PWB + (ch & 1) * 30720;
        #pragma unroll
        for (int i = 0; i < 4; i++) {
            int f4 = tid + 256*i; int r = f4 >> 3, c4 = (f4 & 7) * 4;
            u32t h0, l0, h1, l1;
            split_pair(vx[i].x, vx[i].y, h0, l0);
            split_pair(vx[i].z, vx[i].w, h1, l1);
            char* ph = smem + PXH + r*80 + c4*2;
            char* pl = smem + PXL + r*80 + c4*2;
            *(u32t*)ph = h0; *(u32t*)(ph+4) = h1;
            *(u32t*)pl = l0; *(u32t*)(pl+4) = l1;
        }
        cpa_wait0();
        __syncthreads();

        if (ch < 31) {
            const int k0n = (ch + 1) * 32;
            const int c16 = (ch + 1) * 16;
            #pragma unroll
            for (int i = 0; i < 4; i++) {
                int f4 = tid + 256*i; int r = f4 >> 3, c4 = (f4 & 7) * 4;
                vx[i] = *(const float4*)&x[(size_t)(row0 + r)*C_ + k0n + c4];
            }
            const u32t nb = sb + PWB + ((ch + 1) & 1) * 30720;
            #pragma unroll
            for (int i = 0; i < 3; i++) {
                int id = tid + 256*i;
                int r = id >> 2, seg = id & 3;
                cpa16(nb + r*80 + seg*16,         g_wh + r*512 + c16 + seg*4);
                cpa16(nb + 15360 + r*80 + seg*16, g_wl + r*512 + c16 + seg*4);
            }
            cpa_commit();
        }

        u32t xh[2][4], xl[2][4];
        #pragma unroll
        for (int s = 0; s < 2; s++) {
            u32t ab = (u32t)((16*wid + a_row)*80 + (a_c8 + 16*s)*2);
            ldsm_x4(xh[s], sb + PXH + ab);
            ldsm_x4(xl[s], sb + PXL + ab);
        }
        // accumulator-major: s outer, jp inner (24-MMA spacing per accumulator)
        #pragma unroll
        for (int s = 0; s < 2; s++) {
            #pragma unroll
            for (int jp = 0; jp < 12; jp++) {
                u32t bb = (u32t)((16*jp + b_row)*80 + (b_c8 + 16*s)*2);
                u32t bh[4], bl[4];
                ldsm_x4(bh, wb + bb);
                ldsm_x4(bl, wb + 15360 + bb);
                mma16816(acc[2*jp],   xh[s], bh[0], bh[1]);
                mma16816(acc[2*jp+1], xh[s], bh[2], bh[3]);
                mma16816(acc[2*jp],   xh[s], bl[0], bl[1]);
                mma16816(acc[2*jp+1], xh[s], bl[2], bl[3]);
                mma16816(acc[2*jp],   xl[s], bh[0], bh[1]);
                mma16816(acc[2*jp+1], xl[s], bh[2], bh[3]);
            }
        }
        __syncthreads();
    }

    // epilogue: q scaled by 0.125 (attention scale folded in)
    const int q = lane & 3, r = lane >> 2;
    #pragma unroll
    for (int t = 0; t < 24; t++) {
        int uc = 4*(t & 7) + q;
        size_t rw = (size_t)(row0 + 16*wid + r);
        if (t < 8) {                        // q: scale then bf16 hi/lo
            u32t h0, l0, h1, l1;
            split_pair(acc[t][0]*0.125f, acc[t][1]*0.125f, h0, l0);
            split_pair(acc[t][2]*0.125f, acc[t][3]*0.125f, h1, l1);
            g_qh[rw*32 + uc] = h0;      g_ql[rw*32 + uc] = l0;
            g_qh[(rw+8)*32 + uc] = h1;  g_ql[(rw+8)*32 + uc] = l1;
        } else if (t < 16) {                // k: bf16 hi/lo
            u32t h0, l0, h1, l1;
            split_pair(acc[t][0], acc[t][1], h0, l0);
            split_pair(acc[t][2], acc[t][3], h1, l1);
            g_kh[rw*32 + uc] = h0;      g_kl[rw*32 + uc] = l0;
            g_kh[(rw+8)*32 + uc] = h1;  g_kl[(rw+8)*32 + uc] = l1;
        } else {                            // v: fp16
            g_vf[rw*32 + uc]     = h2pack(acc[t][0], acc[t][1]);
            g_vf[(rw+8)*32 + uc] = h2pack(acc[t][2], acc[t][3]);
        }
    }
}

// ---------------------------------------------------------------------------
// Kernel 2: flash-attention. S = QK^T in bf16 3-term split (Q pre-scaled),
// PV in single-term fp16. Causal, paired, split-KV across 2 warpgroups,
// cp.async double-buffered staging. MMA loops accumulator-major.
// grid = (32, B), block = 256.
// ---------------------------------------------------------------------------
#define AQH 0
#define AQL 9216
#define AKV 18432          // per-buffer: KH 0, KL 9216, VF 18432
#define KVB 27648
#define GRP_BYTES (18432 + 2*KVB)          // 73728
#define MRG_MD (2*GRP_BYTES)               // 147456
#define MRG_OD (MRG_MD + 2048)
#define ATTN_SMEM (MRG_OD + 16384)         // 165888

__global__ __launch_bounds__(256) void attn_tc_kernel(float* __restrict__ out)
{
    extern __shared__ char smem[];
    const int tid  = threadIdx.x;
    const int g    = tid >> 7;
    const int ltid = tid & 127;
    const int wid  = ltid >> 5;
    const int lane = tid & 31;
    const int b    = blockIdx.y;
    const int pr   = blockIdx.x;
    const int q    = lane & 3;
    const int r    = lane >> 2;

    const u32t sbg = smem_u32(smem) + g * GRP_BYTES;

    const int a_row = (lane & 15);
    const int a_c8  = ((lane >> 4) & 1) * 8;
    const int b_row = (lane & 7) + ((lane >> 4) & 1) * 8;
    const int b_c8  = ((lane >> 3) & 1) * 8;
    const int v_row = (lane & 7) + ((lane >> 3) & 1) * 8;
    const int v_c8  = ((lane >> 4) & 1) * 8;

    float* MD = (float*)(smem + MRG_MD);
    float* OD = (float*)(smem + MRG_OD);

    #pragma unroll 1
    for (int half = 0; half < 2; half++) {
        const int m0 = (half == 0 ? pr : 63 - pr) * 64;
        const int nt = m0/64 + 1;
        const int hsp = (nt + 1) >> 1;
        const int tb = g ? hsp : 0;
        const int te = g ? nt  : hsp;

        {
            const size_t qr = (size_t)(b*T_ + m0) * 32;
            stage_tile_async(g_qh + qr, sbg + AQH, ltid);
            stage_tile_async(g_ql + qr, sbg + AQL, ltid);
            if (tb < te) {
                const size_t kr = (size_t)(b*T_ + tb*64) * 32;
                u32t kb = sbg + AKV;
                stage_tile_async(g_kh + kr, kb,         ltid);
                stage_tile_async(g_kl + kr, kb + 9216,  ltid);
                stage_tile_async(g_vf + kr, kb + 18432, ltid);
            }
            cpa_commit();
            cpa_wait0();
            asm volatile("bar.sync %0, 128;" :: "r"(g+1) : "memory");
        }

        u32t qh[4][4], ql[4][4];
        #pragma unroll
        for (int s = 0; s < 4; s++) {
            u32t ab = (u32t)((16*wid + a_row)*144 + (a_c8 + 16*s)*2);
            ldsm_x4(qh[s], sbg + AQH + ab);
            ldsm_x4(ql[s], sbg + AQL + ab);
        }

        float o[8][4] = {};
        float m_i0 = -INFINITY, m_i1 = -INFINITY, l_i0 = 0.f, l_i1 = 0.f;
        const int row0g = m0 + 16*wid + r;
        const int row1g = row0g + 8;

        for (int t = tb; t < te; t++) {
            const int n0 = t * 64;
            const int cur = (t - tb) & 1;
            const u32t cb = sbg + AKV + cur * KVB;

            if (t + 1 < te) {
                const size_t kr = (size_t)(b*T_ + (t+1)*64) * 32;
                u32t nb = sbg + AKV + (cur ^ 1) * KVB;
                stage_tile_async(g_kh + kr, nb,         ltid);
                stage_tile_async(g_kl + kr, nb + 9216,  ltid);
                stage_tile_async(g_vf + kr, nb + 18432, ltid);
                cpa_commit();
                cpa_wait1();
            } else {
                cpa_wait0();
            }
            asm volatile("bar.sync %0, 128;" :: "r"(g+1) : "memory");

            // ---- S = Q K^T (bf16 3-term, accumulator-major order) ----
            float sf[8][4] = {};
            #pragma unroll
            for (int s = 0; s < 4; s++) {
                #pragma unroll
                for (int jp = 0; jp < 4; jp++) {
                    u32t bb = (u32t)((16*jp + b_row)*144 + (b_c8 + 16*s)*2);
                    u32t bh[4], bl[4];
                    ldsm_x4(bh, cb + bb);
                    ldsm_x4(bl, cb + 9216 + bb);
                    mma16816(sf[2*jp],   qh[s], bh[0], bh[1]);
                    mma16816(sf[2*jp+1], qh[s], bh[2], bh[3]);
                    mma16816(sf[2*jp],   qh[s], bl[0], bl[1]);
                    mma16816(sf[2*jp+1], qh[s], bl[2], bl[3]);
                    mma16816(sf[2*jp],   ql[s], bh[0], bh[1]);
                    mma16816(sf[2*jp+1], ql[s], bh[2], bh[3]);
                }
            }

            // ---- causal mask (scale pre-folded into Q) ----
            if (n0 == m0) {
                #pragma unroll
                for (int j = 0; j < 8; j++) {
                    int c = n0 + 8*j + 2*q;
                    if (c   > row0g) sf[j][0] = -INFINITY;
                    if (c+1 > row0g) sf[j][1] = -INFINITY;
                    if (c   > row1g) sf[j][2] = -INFINITY;
                    if (c+1 > row1g) sf[j][3] = -INFINITY;
                }
            }

            // ---- online softmax ----
            float mx0 = -INFINITY, mx1 = -INFINITY;
            #pragma unroll
            for (int j = 0; j < 8; j++) {
                mx0 = fmaxf(mx0, fmaxf(sf[j][0], sf[j][1]));
                mx1 = fmaxf(mx1, fmaxf(sf[j][2], sf[j][3]));
            }
            mx0 = fmaxf(mx0, __shfl_xor_sync(0xffffffffu, mx0, 1));
            mx0 = fmaxf(mx0, __shfl_xor_sync(0xffffffffu, mx0, 2));
            mx1 = fmaxf(mx1, __shfl_xor_sync(0xffffffffu, mx1, 1));
            mx1 = fmaxf(mx1, __shfl_xor_sync(0xffffffffu, mx1, 2));
            float mn0 = fmaxf(m_i0, mx0);
            float mn1 = fmaxf(m_i1, mx1);
            float al0 = __expf(m_i0 - mn0);
            float al1 = __expf(m_i1 - mn1);

            float rs0 = 0.f, rs1 = 0.f;
            u32t pa[4][4];
            #pragma unroll
            for (int j = 0; j < 8; j++) {
                float p0 = __expf(sf[j][0] - mn0);
                float p1 = __expf(sf[j][1] - mn0);
                float p2 = __expf(sf[j][2] - mn1);
                float p3 = __expf(sf[j][3] - mn1);
                rs0 += p0 + p1; rs1 += p2 + p3;
                int t0 = j >> 1, hi2 = (j & 1) * 2;
                pa[t0][hi2]   = h2pack(p0, p1);
                pa[t0][hi2+1] = h2pack(p2, p3);
            }
            rs0 += __shfl_xor_sync(0xffffffffu, rs0, 1);
            rs0 += __shfl_xor_sync(0xffffffffu, rs0, 2);
            rs1 += __shfl_xor_sync(0xffffffffu, rs1, 1);
            rs1 += __shfl_xor_sync(0xffffffffu, rs1, 2);
            l_i0 = l_i0*al0 + rs0;  m_i0 = mn0;
            l_i1 = l_i1*al1 + rs1;  m_i1 = mn1;
            #pragma unroll
            for (int j = 0; j < 8; j++) {
                o[j][0] *= al0; o[j][1] *= al0;
                o[j][2] *= al1; o[j][3] *= al1;
            }

            // ---- O += P V (fp16, accumulator-major order) ----
            #pragma unroll
            for (int t0 = 0; t0 < 4; t0++) {
                #pragma unroll
                for (int jp = 0; jp < 4; jp++) {
                    u32t vb = (u32t)((16*t0 + v_row)*144 + (16*jp + v_c8)*2);
                    u32t vh[4];
                    ldsm_x4_t(vh, cb + 18432 + vb);
                    mma16816h(o[2*jp],   pa[t0], vh[0], vh[1]);
                    mma16816h(o[2*jp+1], pa[t0], vh[2], vh[3]);
                }
            }
            asm volatile("bar.sync %0, 128;" :: "r"(g+1) : "memory");
        }

        // ---- merge partials across the two groups ----
        if (g == 1) {
            MD[ltid*4+0] = m_i0; MD[ltid*4+1] = m_i1;
            MD[ltid*4+2] = l_i0; MD[ltid*4+3] = l_i1;
            #pragma unroll
            for (int j = 0; j < 8; j++)
                #pragma unroll
                for (int e = 0; e < 4; e++)
                    OD[ltid*32 + j*4 + e] = o[j][e];
        }
        __syncthreads();
        if (g == 0) {
            float m1_0 = MD[ltid*4+0], m1_1 = MD[ltid*4+1];
            float l1_0 = MD[ltid*4+2], l1_1 = MD[ltid*4+3];
            float mn0 = fmaxf(m_i0, m1_0);
            float mn1 = fmaxf(m_i1, m1_1);
            float a0 = __expf(m_i0 - mn0), b0 = __expf(m1_0 - mn0);
            float a1 = __expf(m_i1 - mn1), b1 = __expf(m1_1 - mn1);
            float lt0 = l_i0*a0 + l1_0*b0;
            float lt1 = l_i1*a1 + l1_1*b1;
            float inv0 = 1.0f / lt0;
            float inv1 = 1.0f / lt1;
            float* ob = out + (size_t)(b*T_) * H_;
            #pragma unroll
            for (int j = 0; j < 8; j++) {
                int col = 8*j + 2*q;
                float o0 = (o[j][0]*a0 + OD[ltid*32 + j*4 + 0]*b0) * inv0;
                float o1 = (o[j][1]*a0 + OD[ltid*32 + j*4 + 1]*b0) * inv0;
                float o2 = (o[j][2]*a1 + OD[ltid*32 + j*4 + 2]*b1) * inv1;
                float o3 = (o[j][3]*a1 + OD[ltid*32 + j*4 + 3]*b1) * inv1;
                *(float2*)&ob[(size_t)row0g*H_ + col] = make_float2(o0, o1);
                *(float2*)&ob[(size_t)row1g*H_ + col] = make_float2(o2, o3);
            }
        }
        __syncthreads();
    }
}

// ---------------------------------------------------------------------------
extern "C" void kernel_launch(void* const* d_in, const int* in_sizes, int n_in,
                              void* d_out, int out_size)
{
    const float* x  = (const float*)d_in[0];
    const float* Wq = (const float*)d_in[1];
    const float* Wk = (const float*)d_in[2];
    const float* Wv = (const float*)d_in[3];
    float* out = (float*)d_out;

    cudaFuncSetAttribute(proj_tc_kernel,
                         cudaFuncAttributeMaxDynamicSharedMemorySize, PROJ_SMEM);
    cudaFuncSetAttribute(attn_tc_kernel,
                         cudaFuncAttributeMaxDynamicSharedMemorySize, ATTN_SMEM);

    wsplit_kernel<<<384, 256>>>(Wq, Wk, Wv);
    proj_tc_kernel<<<BT/128, 256, PROJ_SMEM>>>(x);
    attn_tc_kernel<<<dim3(32, B_), 256, ATTN_SMEM>>>(out);
}